// round 1
// baseline (speedup 1.0000x reference)
#include <cuda_runtime.h>
#include <math.h>

#define CC   64
#define C8   8
#define NN   9216
#define BB   2
#define LOG2E 1.44269504088896340736f

// Scratch (no allocations allowed in kernel_launch)
__device__ float g_sigma[3];
__device__ float g_f[BB * C8 * NN];   // keys   [B, 8, N]
__device__ float g_g[BB * C8 * NN];   // queries[B, 8, N]
__device__ float g_h[BB * CC * NN];   // values [B, 64, N]

// ---------------------------------------------------------------------------
// Kernel 1: spectral norms via power iteration on Gram matrix G = W W^T.
// block 0: Wq (8x64), block 1: Wk (8x64), block 2: Wv (64x64). 64 threads.
// ---------------------------------------------------------------------------
__global__ void sigma_kernel(const float* __restrict__ Wq,
                             const float* __restrict__ Wk,
                             const float* __restrict__ Wv) {
    __shared__ float G[64 * 64];
    __shared__ float v[64];
    __shared__ float s_nrm;
    const int bid = blockIdx.x;
    const int tid = threadIdx.x;
    const float* W = (bid == 0) ? Wq : ((bid == 1) ? Wk : Wv);
    const int R = (bid == 2) ? 64 : 8;

    for (int e = tid; e < R * R; e += 64) {
        int r = e / R, c = e % R;
        float s = 0.f;
        #pragma unroll 16
        for (int k = 0; k < 64; k++) s += W[r * 64 + k] * W[c * 64 + k];
        G[e] = s;
    }
    if (tid < R) v[tid] = 1.f;
    __syncthreads();

    for (int it = 0; it < 150; it++) {
        float s = 0.f;
        if (tid < R) {
            for (int k = 0; k < R; k++) s += G[tid * R + k] * v[k];
        }
        __syncthreads();
        if (tid < R) v[tid] = s;
        __syncthreads();
        if (tid == 0) {
            float ss = 0.f;
            for (int k = 0; k < R; k++) ss += v[k] * v[k];
            s_nrm = sqrtf(ss);
        }
        __syncthreads();
        if (tid < R) v[tid] *= (1.f / s_nrm);
        __syncthreads();
    }
    // v normalized, ||G v|| = lambda = sigma^2
    if (tid == 0) g_sigma[bid] = sqrtf(s_nrm);
}

// ---------------------------------------------------------------------------
// Kernel 2: 1x1-conv projections f, g, h with spectrally-normalized weights.
// One thread per (b, n). 256 threads/block, 72 blocks.
// ---------------------------------------------------------------------------
__global__ __launch_bounds__(256)
void proj_kernel(const float* __restrict__ x,
                 const float* __restrict__ Wq, const float* __restrict__ bq,
                 const float* __restrict__ Wk, const float* __restrict__ bk,
                 const float* __restrict__ Wv, const float* __restrict__ bv) {
    __shared__ float sWq[C8 * CC], sWk[C8 * CC], sWv[CC * CC];
    __shared__ float sbq[C8], sbk[C8], sbv[CC];

    const int tid = threadIdx.x;
    const float isq = 1.f / g_sigma[0];
    const float isk = 1.f / g_sigma[1];
    const float isv = 1.f / g_sigma[2];

    for (int e = tid; e < C8 * CC; e += 256) { sWq[e] = Wq[e] * isq; sWk[e] = Wk[e] * isk; }
    for (int e = tid; e < CC * CC; e += 256) { sWv[e] = Wv[e] * isv; }
    if (tid < C8) { sbq[tid] = bq[tid]; sbk[tid] = bk[tid]; }
    if (tid < CC) { sbv[tid] = bv[tid]; }
    __syncthreads();

    const int t = blockIdx.x * 256 + tid;
    const int b = t / NN;
    const int n = t % NN;

    float xr[CC];
    #pragma unroll
    for (int c = 0; c < CC; c++) xr[c] = x[(b * CC + c) * NN + n];

    #pragma unroll
    for (int o = 0; o < C8; o++) {
        float sf = sbq[o], sg = sbk[o];
        #pragma unroll
        for (int k = 0; k < CC; k++) {
            sf += sWq[o * CC + k] * xr[k];
            sg += sWk[o * CC + k] * xr[k];
        }
        g_f[(b * C8 + o) * NN + n] = sf;
        g_g[(b * C8 + o) * NN + n] = sg;
    }
    #pragma unroll 4
    for (int o = 0; o < CC; o++) {
        float s = sbv[o];
        #pragma unroll
        for (int k = 0; k < CC; k++) s += sWv[o * CC + k] * xr[k];
        g_h[(b * CC + o) * NN + n] = s;
    }
}

// ---------------------------------------------------------------------------
// Kernel 3: flash attention. Each thread owns one output position j
// (query = g[:,j], dim 8), streams over all keys i with online softmax,
// accumulates 64-dim value vector in registers.
// grid = (72, 2), 128 threads.
// ---------------------------------------------------------------------------
__global__ __launch_bounds__(128)
void attn_kernel(const float* __restrict__ x,
                 const float* __restrict__ gamma,
                 float* __restrict__ out) {
    constexpr int TK = 128;
    __shared__ float sK[TK][12];   // padded: 4-way STS conflicts max, fp4-aligned
    __shared__ float sV[TK][68];   // padded

    const int b = blockIdx.y;
    const int j = blockIdx.x * 128 + threadIdx.x;

    float q[C8];
    #pragma unroll
    for (int c = 0; c < C8; c++) q[c] = g_g[(b * C8 + c) * NN + j];

    float m = -1e30f, l = 0.f;
    float acc[CC];
    #pragma unroll
    for (int c = 0; c < CC; c++) acc[c] = 0.f;

    for (int i0 = 0; i0 < NN; i0 += TK) {
        __syncthreads();
        #pragma unroll
        for (int e = threadIdx.x; e < TK * C8; e += 128) {
            int c = e >> 7, i = e & 127;
            sK[i][c] = g_f[(b * C8 + c) * NN + i0 + i];
        }
        #pragma unroll
        for (int e = threadIdx.x; e < TK * CC; e += 128) {
            int c = e >> 7, i = e & 127;
            sV[i][c] = g_h[(b * CC + c) * NN + i0 + i];
        }
        __syncthreads();

        #pragma unroll 2
        for (int i = 0; i < TK; i++) {
            float4 k0 = *(const float4*)&sK[i][0];
            float4 k1 = *(const float4*)&sK[i][4];
            // tree-reduced dot (shorter dependency chain than linear fma chain)
            float s = ((q[0] * k0.x + q[1] * k0.y) + (q[2] * k0.z + q[3] * k0.w))
                    + ((q[4] * k1.x + q[5] * k1.y) + (q[6] * k1.z + q[7] * k1.w));
            if (s > m) {
                float sc = exp2f((m - s) * LOG2E);  // first iter: exp2(-inf)=0
                m = s;
                l *= sc;
                #pragma unroll
                for (int c = 0; c < CC; c++) acc[c] *= sc;
            }
            float p = exp2f((s - m) * LOG2E);
            l += p;
            #pragma unroll
            for (int c = 0; c < CC; c += 4) {
                float4 vv = *(const float4*)&sV[i][c];
                acc[c]     += p * vv.x;
                acc[c + 1] += p * vv.y;
                acc[c + 2] += p * vv.z;
                acc[c + 3] += p * vv.w;
            }
        }
    }

    const float gm  = gamma[0];
    const float inv = 1.f / l;
    #pragma unroll
    for (int c = 0; c < CC; c++) {
        const int idx = (b * CC + c) * NN + j;
        out[idx] = gm * acc[c] * inv + x[idx];
    }
}

// ---------------------------------------------------------------------------
extern "C" void kernel_launch(void* const* d_in, const int* in_sizes, int n_in,
                              void* d_out, int out_size) {
    const float* x     = (const float*)d_in[0];
    const float* Wq    = (const float*)d_in[1];
    const float* bq    = (const float*)d_in[2];
    const float* Wk    = (const float*)d_in[3];
    const float* bk    = (const float*)d_in[4];
    const float* Wv    = (const float*)d_in[5];
    const float* bv    = (const float*)d_in[6];
    const float* gamma = (const float*)d_in[7];
    float* out = (float*)d_out;

    sigma_kernel<<<3, 64>>>(Wq, Wk, Wv);
    proj_kernel<<<(BB * NN) / 256, 256>>>(x, Wq, bq, Wk, bk, Wv, bv);
    attn_kernel<<<dim3(NN / 128, BB), 128>>>(x, gamma, out);
}

// round 2
// speedup vs baseline: 1.3664x; 1.3664x over previous
#include <cuda_runtime.h>
#include <math.h>

#define CC   64
#define C8   8
#define NN   9216
#define BB   2
#define LOG2E 1.44269504088896340736f

// Scratch (no allocations allowed in kernel_launch)
__device__ float g_sigma[3];
__device__ float g_f[BB * C8 * NN];   // keys   [B, 8, N]
__device__ float g_g[BB * C8 * NN];   // queries[B, 8, N]
__device__ float g_h[BB * CC * NN];   // values [B, 64, N]

// ---------------------------------------------------------------------------
// Kernel 1: spectral norms via power iteration on Gram matrix G = W W^T.
// Gram row lives in registers (one row per thread); norm via shuffle reduce.
// block 0: Wq (8x64), block 1: Wk (8x64), block 2: Wv (64x64). 64 threads.
// ---------------------------------------------------------------------------
__global__ __launch_bounds__(64)
void sigma_kernel(const float* __restrict__ Wq,
                  const float* __restrict__ Wk,
                  const float* __restrict__ Wv) {
    __shared__ float sW[64 * 64];
    __shared__ float v[64];
    __shared__ float red[2];
    const int bid = blockIdx.x;
    const int tid = threadIdx.x;
    const float* W = (bid == 0) ? Wq : ((bid == 1) ? Wk : Wv);
    const int R = (bid == 2) ? 64 : 8;

    for (int e = tid; e < R * 64; e += 64) sW[e] = W[e];
    if (tid < R) v[tid] = 1.f;
    __syncthreads();

    // Build my Gram row in registers: Gr[c] = <W[tid,:], W[c,:]>
    float Gr[64];
    if (tid < R) {
        float wr[64];
        #pragma unroll
        for (int k = 0; k < 64; k++) wr[k] = sW[tid * 64 + k];
        for (int c = 0; c < R; c++) {
            float s = 0.f;
            #pragma unroll
            for (int k = 0; k < 64; k++) s += wr[k] * sW[c * 64 + k];  // broadcast read
            Gr[c] = s;
        }
    }
    __syncthreads();

    float lam = 1.f;
    for (int it = 0; it < 100; it++) {
        float s = 0.f;
        if (tid < R) {
            for (int k = 0; k < R; k++) s += Gr[k] * v[k];             // broadcast read
        }
        float sq = (tid < R) ? s * s : 0.f;
        #pragma unroll
        for (int off = 16; off > 0; off >>= 1)
            sq += __shfl_xor_sync(0xffffffff, sq, off);
        if ((tid & 31) == 0) red[tid >> 5] = sq;
        __syncthreads();
        float nrm = sqrtf(red[0] + red[1]);
        lam = nrm;                       // ||G v|| -> lambda_max = sigma^2
        if (tid < R) v[tid] = s / nrm;
        __syncthreads();
    }
    if (tid == 0) g_sigma[bid] = sqrtf(lam);
}

// ---------------------------------------------------------------------------
// Kernel 2: 1x1-conv projections f, g, h with spectrally-normalized weights.
// One thread per (b, n). 256 threads/block, 72 blocks.
// ---------------------------------------------------------------------------
__global__ __launch_bounds__(256)
void proj_kernel(const float* __restrict__ x,
                 const float* __restrict__ Wq, const float* __restrict__ bq,
                 const float* __restrict__ Wk, const float* __restrict__ bk,
                 const float* __restrict__ Wv, const float* __restrict__ bv) {
    __shared__ float sWq[C8 * CC], sWk[C8 * CC], sWv[CC * CC];
    __shared__ float sbq[C8], sbk[C8], sbv[CC];

    const int tid = threadIdx.x;
    const float isq = 1.f / g_sigma[0];
    const float isk = 1.f / g_sigma[1];
    const float isv = 1.f / g_sigma[2];

    for (int e = tid; e < C8 * CC; e += 256) { sWq[e] = Wq[e] * isq; sWk[e] = Wk[e] * isk; }
    for (int e = tid; e < CC * CC; e += 256) { sWv[e] = Wv[e] * isv; }
    if (tid < C8) { sbq[tid] = bq[tid]; sbk[tid] = bk[tid]; }
    if (tid < CC) { sbv[tid] = bv[tid]; }
    __syncthreads();

    const int t = blockIdx.x * 256 + tid;
    const int b = t / NN;
    const int n = t % NN;

    float xr[CC];
    #pragma unroll
    for (int c = 0; c < CC; c++) xr[c] = x[(b * CC + c) * NN + n];

    #pragma unroll
    for (int o = 0; o < C8; o++) {
        float sf = sbq[o], sg = sbk[o];
        #pragma unroll
        for (int k = 0; k < CC; k++) {
            sf += sWq[o * CC + k] * xr[k];
            sg += sWk[o * CC + k] * xr[k];
        }
        g_f[(b * C8 + o) * NN + n] = sf;
        g_g[(b * C8 + o) * NN + n] = sg;
    }
    #pragma unroll 4
    for (int o = 0; o < CC; o++) {
        float s = sbv[o];
        #pragma unroll
        for (int k = 0; k < CC; k++) s += sWv[o * CC + k] * xr[k];
        g_h[(b * CC + o) * NN + n] = s;
    }
}

// ---------------------------------------------------------------------------
// Kernel 3: flash attention. Each thread owns one output position j
// (query = g[:,j], dim 8, pre-scaled by log2(e)), streams over all keys i
// with online softmax in the exp2 domain, 64-dim value accumulator in regs.
// grid = (72, 2), 128 threads.
// ---------------------------------------------------------------------------
__global__ __launch_bounds__(128)
void attn_kernel(const float* __restrict__ x,
                 const float* __restrict__ gamma,
                 float* __restrict__ out) {
    constexpr int TK = 128;
    __shared__ float sK[TK][12];   // padded
    __shared__ float sV[TK][68];   // padded

    const int b = blockIdx.y;
    const int j = blockIdx.x * 128 + threadIdx.x;

    float q[C8];
    #pragma unroll
    for (int c = 0; c < C8; c++) q[c] = g_g[(b * C8 + c) * NN + j] * LOG2E;

    float m = -1e30f, l = 0.f;
    float acc[CC];
    #pragma unroll
    for (int c = 0; c < CC; c++) acc[c] = 0.f;

    for (int i0 = 0; i0 < NN; i0 += TK) {
        __syncthreads();
        #pragma unroll
        for (int e = threadIdx.x; e < TK * C8; e += 128) {
            int c = e >> 7, i = e & 127;
            sK[i][c] = g_f[(b * C8 + c) * NN + i0 + i];
        }
        #pragma unroll
        for (int e = threadIdx.x; e < TK * CC; e += 128) {
            int c = e >> 7, i = e & 127;
            sV[i][c] = g_h[(b * CC + c) * NN + i0 + i];
        }
        __syncthreads();

        #pragma unroll 2
        for (int i = 0; i < TK; i++) {
            float4 k0 = *(const float4*)&sK[i][0];
            float4 k1 = *(const float4*)&sK[i][4];
            // s is already in log2 domain (q pre-scaled)
            float s = ((q[0] * k0.x + q[1] * k0.y) + (q[2] * k0.z + q[3] * k0.w))
                    + ((q[4] * k1.x + q[5] * k1.y) + (q[6] * k1.z + q[7] * k1.w));
            if (s > m) {
                float sc = exp2f(m - s);   // first iter: exp2(-inf)=0
                m = s;
                l *= sc;
                #pragma unroll
                for (int c = 0; c < CC; c++) acc[c] *= sc;
            }
            float p = exp2f(s - m);
            l += p;
            #pragma unroll
            for (int c = 0; c < CC; c += 4) {
                float4 vv = *(const float4*)&sV[i][c];
                acc[c]     += p * vv.x;
                acc[c + 1] += p * vv.y;
                acc[c + 2] += p * vv.z;
                acc[c + 3] += p * vv.w;
            }
        }
    }

    const float gm  = gamma[0];
    const float inv = 1.f / l;
    #pragma unroll
    for (int c = 0; c < CC; c++) {
        const int idx = (b * CC + c) * NN + j;
        out[idx] = gm * acc[c] * inv + x[idx];
    }
}

// ---------------------------------------------------------------------------
extern "C" void kernel_launch(void* const* d_in, const int* in_sizes, int n_in,
                              void* d_out, int out_size) {
    const float* x     = (const float*)d_in[0];
    const float* Wq    = (const float*)d_in[1];
    const float* bq    = (const float*)d_in[2];
    const float* Wk    = (const float*)d_in[3];
    const float* bk    = (const float*)d_in[4];
    const float* Wv    = (const float*)d_in[5];
    const float* bv    = (const float*)d_in[6];
    const float* gamma = (const float*)d_in[7];
    float* out = (float*)d_out;

    sigma_kernel<<<3, 64>>>(Wq, Wk, Wv);
    proj_kernel<<<(BB * NN) / 256, 256>>>(x, Wq, bq, Wk, bk, Wv, bv);
    attn_kernel<<<dim3(NN / 128, BB), 128>>>(x, gamma, out);
}

// round 3
// speedup vs baseline: 1.5298x; 1.1196x over previous
#include <cuda_runtime.h>
#include <math.h>
#include <stdint.h>

#define CC     64
#define C8     8
#define NN     9216
#define BB     2
#define SPLITS 4
#define KPS    (NN / SPLITS)    // 2304 keys per split
#define TK     128
#define LOG2E  1.44269504088896340736f

// Scratch (no allocations allowed in kernel_launch)
__device__ float g_sigma[3];
__device__ float g_f[BB * C8 * NN];              // keys   [B, 8, N]
__device__ float g_g[BB * C8 * NN];              // queries[B, 8, N]
__device__ float g_h[BB * CC * NN];              // values [B, 64, N]
__device__ float g_pm[BB * SPLITS * NN];         // split partial max (log2 domain)
__device__ float g_pl[BB * SPLITS * NN];         // split partial denom
__device__ float g_pacc[BB * SPLITS * CC * NN];  // split partial numerators

// ---- Blackwell packed f32x2 helpers (SASS FFMA2: double fp32 FMA rate) ----
__device__ __forceinline__ uint64_t pack2(float lo, float hi) {
    uint64_t r; asm("mov.b64 %0, {%1, %2};" : "=l"(r) : "f"(lo), "f"(hi)); return r;
}
__device__ __forceinline__ uint64_t ffma2(uint64_t a, uint64_t b, uint64_t c) {
    uint64_t d; asm("fma.rn.f32x2 %0, %1, %2, %3;" : "=l"(d) : "l"(a), "l"(b), "l"(c)); return d;
}
__device__ __forceinline__ uint64_t fmul2(uint64_t a, uint64_t b) {
    uint64_t d; asm("mul.rn.f32x2 %0, %1, %2;" : "=l"(d) : "l"(a), "l"(b)); return d;
}
__device__ __forceinline__ void unpack2(uint64_t v, float& lo, float& hi) {
    asm("mov.b64 {%0, %1}, %2;" : "=f"(lo), "=f"(hi) : "l"(v));
}

// ---------------------------------------------------------------------------
// Kernel 1: spectral norms via power iteration on Gram matrix G = W W^T.
// ---------------------------------------------------------------------------
__global__ __launch_bounds__(64)
void sigma_kernel(const float* __restrict__ Wq,
                  const float* __restrict__ Wk,
                  const float* __restrict__ Wv) {
    __shared__ float sW[64 * 64];
    __shared__ float v[64];
    __shared__ float red[2];
    const int bid = blockIdx.x;
    const int tid = threadIdx.x;
    const float* W = (bid == 0) ? Wq : ((bid == 1) ? Wk : Wv);
    const int R = (bid == 2) ? 64 : 8;

    for (int e = tid; e < R * 64; e += 64) sW[e] = W[e];
    if (tid < R) v[tid] = 1.f;
    __syncthreads();

    // My Gram row in registers (4-way ILP dots)
    float Gr[64];
    if (tid < R) {
        float wr[64];
        #pragma unroll
        for (int k = 0; k < 64; k++) wr[k] = sW[tid * 64 + k];
        for (int c = 0; c < R; c++) {
            float s0 = 0.f, s1 = 0.f, s2 = 0.f, s3 = 0.f;
            #pragma unroll
            for (int k = 0; k < 64; k += 4) {
                s0 += wr[k]     * sW[c * 64 + k];
                s1 += wr[k + 1] * sW[c * 64 + k + 1];
                s2 += wr[k + 2] * sW[c * 64 + k + 2];
                s3 += wr[k + 3] * sW[c * 64 + k + 3];
            }
            Gr[c] = (s0 + s1) + (s2 + s3);
        }
    }
    __syncthreads();

    float lam = 1.f;
    for (int it = 0; it < 100; it++) {
        float s = 0.f;
        if (tid < R) {
            float a0 = 0.f, a1 = 0.f, a2 = 0.f, a3 = 0.f;
            for (int k = 0; k < R; k += 4) {
                a0 += Gr[k]     * v[k];
                a1 += Gr[k + 1] * v[k + 1];
                a2 += Gr[k + 2] * v[k + 2];
                a3 += Gr[k + 3] * v[k + 3];
            }
            s = (a0 + a1) + (a2 + a3);
        }
        float sq = (tid < R) ? s * s : 0.f;
        #pragma unroll
        for (int off = 16; off > 0; off >>= 1)
            sq += __shfl_xor_sync(0xffffffff, sq, off);
        if ((tid & 31) == 0) red[tid >> 5] = sq;
        __syncthreads();
        float nrm = sqrtf(red[0] + red[1]);
        lam = nrm;                        // ||G v|| -> lambda_max = sigma^2
        if (tid < R) v[tid] = s / nrm;
        __syncthreads();
    }
    if (tid == 0) g_sigma[bid] = sqrtf(lam);
}

// ---------------------------------------------------------------------------
// Kernel 2: 1x1-conv projections f, g, h with spectrally-normalized weights.
// ---------------------------------------------------------------------------
__global__ __launch_bounds__(256)
void proj_kernel(const float* __restrict__ x,
                 const float* __restrict__ Wq, const float* __restrict__ bq,
                 const float* __restrict__ Wk, const float* __restrict__ bk,
                 const float* __restrict__ Wv, const float* __restrict__ bv) {
    __shared__ float sWq[C8 * CC], sWk[C8 * CC], sWv[CC * CC];
    __shared__ float sbq[C8], sbk[C8], sbv[CC];

    const int tid = threadIdx.x;
    const float isq = 1.f / g_sigma[0];
    const float isk = 1.f / g_sigma[1];
    const float isv = 1.f / g_sigma[2];

    for (int e = tid; e < C8 * CC; e += 256) { sWq[e] = Wq[e] * isq; sWk[e] = Wk[e] * isk; }
    for (int e = tid; e < CC * CC; e += 256) { sWv[e] = Wv[e] * isv; }
    if (tid < C8) { sbq[tid] = bq[tid]; sbk[tid] = bk[tid]; }
    if (tid < CC) { sbv[tid] = bv[tid]; }
    __syncthreads();

    const int t = blockIdx.x * 256 + tid;
    const int b = t / NN;
    const int n = t % NN;

    float xr[CC];
    #pragma unroll
    for (int c = 0; c < CC; c++) xr[c] = x[(b * CC + c) * NN + n];

    #pragma unroll
    for (int o = 0; o < C8; o++) {
        float sf = sbq[o], sg = sbk[o];
        #pragma unroll
        for (int k = 0; k < CC; k++) {
            sf += sWq[o * CC + k] * xr[k];
            sg += sWk[o * CC + k] * xr[k];
        }
        g_f[(b * C8 + o) * NN + n] = sf;
        g_g[(b * C8 + o) * NN + n] = sg;
    }
    #pragma unroll 4
    for (int o = 0; o < CC; o++) {
        float s = sbv[o];
        #pragma unroll
        for (int k = 0; k < CC; k++) s += sWv[o * CC + k] * xr[k];
        g_h[(b * CC + o) * NN + n] = s;
    }
}

// ---------------------------------------------------------------------------
// Kernel 3: split-K flash attention with packed f32x2 math.
// Thread t owns output position j = blockIdx.x*128 + t; block processes keys
// [sp*KPS, (sp+1)*KPS). Channel PAIRS are packed into f32x2 so the 64-dim PV
// accumulation is 32 FFMA2 per key. Partials (m, l, acc) go to scratch.
// grid = (72, B, SPLITS), 128 threads.
// ---------------------------------------------------------------------------
__global__ __launch_bounds__(128)
void attn_kernel() {
    __shared__ float sK[TK][12];    // padded
    __shared__ float sV[TK][68];    // padded (272B rows, 16B aligned)

    const int b  = blockIdx.y;
    const int sp = blockIdx.z;
    const int j  = blockIdx.x * 128 + threadIdx.x;

    uint64_t q2[4];
    #pragma unroll
    for (int cc = 0; cc < 4; cc++)
        q2[cc] = pack2(g_g[(b * C8 + 2 * cc) * NN + j] * LOG2E,
                       g_g[(b * C8 + 2 * cc + 1) * NN + j] * LOG2E);

    float m = -1e30f, l = 0.f;
    uint64_t acc[32];
    #pragma unroll
    for (int c = 0; c < 32; c++) acc[c] = 0ull;

    const int i_beg = sp * KPS;
    for (int i0 = i_beg; i0 < i_beg + KPS; i0 += TK) {
        __syncthreads();
        #pragma unroll
        for (int e = threadIdx.x; e < TK * C8; e += 128) {
            int c = e >> 7, i = e & 127;
            sK[i][c] = g_f[(b * C8 + c) * NN + i0 + i];
        }
        #pragma unroll
        for (int e = threadIdx.x; e < TK * CC; e += 128) {
            int c = e >> 7, i = e & 127;
            sV[i][c] = g_h[(b * CC + c) * NN + i0 + i];
        }
        __syncthreads();

        #pragma unroll 2
        for (int i = 0; i < TK; i++) {
            const ulonglong2* kr = (const ulonglong2*)&sK[i][0];
            ulonglong2 k0 = kr[0];
            ulonglong2 k1 = kr[1];
            uint64_t s2 = fmul2(q2[0], k0.x);
            s2 = ffma2(q2[1], k0.y, s2);
            s2 = ffma2(q2[2], k1.x, s2);
            s2 = ffma2(q2[3], k1.y, s2);
            float se, so; unpack2(s2, se, so);
            float s = se + so;                 // log2-domain score
            if (s > m) {
                float sc = exp2f(m - s);       // first iter: exp2(-inf)=0
                m = s;
                l *= sc;
                uint64_t sc2 = pack2(sc, sc);
                #pragma unroll
                for (int c = 0; c < 32; c++) acc[c] = fmul2(acc[c], sc2);
            }
            float p = exp2f(s - m);
            l += p;
            uint64_t p2 = pack2(p, p);
            const ulonglong2* vr = (const ulonglong2*)&sV[i][0];
            #pragma unroll
            for (int c = 0; c < 16; c++) {
                ulonglong2 vv = vr[c];
                acc[2 * c]     = ffma2(p2, vv.x, acc[2 * c]);
                acc[2 * c + 1] = ffma2(p2, vv.y, acc[2 * c + 1]);
            }
        }
    }

    const int ps = (b * SPLITS + sp);
    g_pm[ps * NN + j] = m;
    g_pl[ps * NN + j] = l;
    #pragma unroll
    for (int c = 0; c < 32; c++) {
        float a0, a1; unpack2(acc[c], a0, a1);
        g_pacc[(ps * CC + 2 * c)     * NN + j] = a0;
        g_pacc[(ps * CC + 2 * c + 1) * NN + j] = a1;
    }
}

// ---------------------------------------------------------------------------
// Kernel 4: combine split partials, apply gamma + residual.
// grid = 72 blocks x 256 threads over (b, j).
// ---------------------------------------------------------------------------
__global__ __launch_bounds__(256)
void reduce_kernel(const float* __restrict__ x,
                   const float* __restrict__ gamma,
                   float* __restrict__ out) {
    const int t = blockIdx.x * 256 + threadIdx.x;
    const int b = t / NN;
    const int j = t % NN;

    float ms[SPLITS], ls[SPLITS];
    float M = -1e30f;
    #pragma unroll
    for (int s = 0; s < SPLITS; s++) {
        ms[s] = g_pm[(b * SPLITS + s) * NN + j];
        ls[s] = g_pl[(b * SPLITS + s) * NN + j];
        M = fmaxf(M, ms[s]);
    }
    float w[SPLITS], L = 0.f;
    #pragma unroll
    for (int s = 0; s < SPLITS; s++) {
        w[s] = exp2f(ms[s] - M);      // log2 domain
        L += ls[s] * w[s];
    }
    const float inv = gamma[0] / L;

    #pragma unroll 4
    for (int c = 0; c < CC; c++) {
        float a = 0.f;
        #pragma unroll
        for (int s = 0; s < SPLITS; s++)
            a += g_pacc[((b * SPLITS + s) * CC + c) * NN + j] * w[s];
        const int idx = (b * CC + c) * NN + j;
        out[idx] = a * inv + x[idx];
    }
}

// ---------------------------------------------------------------------------
extern "C" void kernel_launch(void* const* d_in, const int* in_sizes, int n_in,
                              void* d_out, int out_size) {
    const float* x     = (const float*)d_in[0];
    const float* Wq    = (const float*)d_in[1];
    const float* bq    = (const float*)d_in[2];
    const float* Wk    = (const float*)d_in[3];
    const float* bk    = (const float*)d_in[4];
    const float* Wv    = (const float*)d_in[5];
    const float* bv    = (const float*)d_in[6];
    const float* gamma = (const float*)d_in[7];
    float* out = (float*)d_out;

    sigma_kernel<<<3, 64>>>(Wq, Wk, Wv);
    proj_kernel<<<(BB * NN) / 256, 256>>>(x, Wq, bq, Wk, bk, Wv, bv);
    attn_kernel<<<dim3(NN / 128, BB, SPLITS), 128>>>();
    reduce_kernel<<<(BB * NN) / 256, 256>>>(x, gamma, out);
}

// round 7
// speedup vs baseline: 2.6631x; 1.7408x over previous
#include <cuda_runtime.h>
#include <math.h>
#include <stdint.h>

#define CC     64
#define C8     8
#define NN     9216
#define BB     2
#define SPLITS 4
#define KPS    (NN / SPLITS)    // 2304 keys per split
#define TK     128
#define KT     8                // key subtile (branchless softmax granularity)
#define LOG2E  1.44269504088896340736f

// Scratch (no allocations allowed in kernel_launch)
__device__ float g_sigma[3];
__device__ float g_f[BB * C8 * NN];              // keys   [B, 8, N]
__device__ float g_g[BB * C8 * NN];              // queries[B, 8, N]
__device__ float g_h[BB * CC * NN];              // values [B, 64, N]
__device__ float g_pm[BB * SPLITS * NN];         // split partial max (log2 domain)
__device__ float g_pl[BB * SPLITS * NN];         // split partial denom
__device__ float g_pacc[BB * SPLITS * CC * NN];  // split partial numerators

// ---- Blackwell packed f32x2 helpers (SASS FFMA2: double fp32 FMA rate) ----
__device__ __forceinline__ uint64_t pack2(float lo, float hi) {
    uint64_t r; asm("mov.b64 %0, {%1, %2};" : "=l"(r) : "f"(lo), "f"(hi)); return r;
}
__device__ __forceinline__ uint64_t ffma2(uint64_t a, uint64_t b, uint64_t c) {
    uint64_t d; asm("fma.rn.f32x2 %0, %1, %2, %3;" : "=l"(d) : "l"(a), "l"(b), "l"(c)); return d;
}
__device__ __forceinline__ uint64_t fmul2(uint64_t a, uint64_t b) {
    uint64_t d; asm("mul.rn.f32x2 %0, %1, %2;" : "=l"(d) : "l"(a), "l"(b)); return d;
}
__device__ __forceinline__ void unpack2(uint64_t v, float& lo, float& hi) {
    asm("mov.b64 {%0, %1}, %2;" : "=f"(lo), "=f"(hi) : "l"(v));
}
// single-instruction MUFU exp2 (2-ulp, flushes large-negative to 0)
__device__ __forceinline__ float ex2(float x) {
    float r; asm("ex2.approx.f32 %0, %1;" : "=f"(r) : "f"(x)); return r;
}

// ---------------------------------------------------------------------------
// Kernel 1: spectral norms via power iteration on Gram matrix G = W W^T.
// ---------------------------------------------------------------------------
__global__ __launch_bounds__(64)
void sigma_kernel(const float* __restrict__ Wq,
                  const float* __restrict__ Wk,
                  const float* __restrict__ Wv) {
    __shared__ float sW[64 * 64];
    __shared__ float v[64];
    __shared__ float red[2];
    const int bid = blockIdx.x;
    const int tid = threadIdx.x;
    const float* W = (bid == 0) ? Wq : ((bid == 1) ? Wk : Wv);
    const int R = (bid == 2) ? 64 : 8;

    for (int e = tid; e < R * 64; e += 64) sW[e] = W[e];
    if (tid < R) v[tid] = 1.f;
    __syncthreads();

    // My Gram row in registers (8-way ILP dots)
    float Gr[64];
    if (tid < R) {
        float wr[64];
        #pragma unroll
        for (int k = 0; k < 64; k++) wr[k] = sW[tid * 64 + k];
        for (int c = 0; c < R; c++) {
            float a[8];
            #pragma unroll
            for (int u = 0; u < 8; u++) a[u] = wr[u] * sW[c * 64 + u];
            #pragma unroll
            for (int k = 8; k < 64; k += 8)
                #pragma unroll
                for (int u = 0; u < 8; u++) a[u] += wr[k + u] * sW[c * 64 + k + u];
            Gr[c] = ((a[0] + a[1]) + (a[2] + a[3])) + ((a[4] + a[5]) + (a[6] + a[7]));
        }
    }
    __syncthreads();

    float lam = 1.f;
    for (int it = 0; it < 70; it++) {
        float s = 0.f;
        if (tid < R) {
            if (R == 8) {
                float a0 = 0.f, a1 = 0.f;
                #pragma unroll
                for (int k = 0; k < 8; k += 2) { a0 += Gr[k] * v[k]; a1 += Gr[k + 1] * v[k + 1]; }
                s = a0 + a1;
            } else {
                float a[8];
                #pragma unroll
                for (int u = 0; u < 8; u++) a[u] = Gr[u] * v[u];
                #pragma unroll
                for (int k = 8; k < 64; k += 8)
                    #pragma unroll
                    for (int u = 0; u < 8; u++) a[u] += Gr[k + u] * v[k + u];
                s = ((a[0] + a[1]) + (a[2] + a[3])) + ((a[4] + a[5]) + (a[6] + a[7]));
            }
        }
        float sq = (tid < R) ? s * s : 0.f;
        #pragma unroll
        for (int off = 16; off > 0; off >>= 1)
            sq += __shfl_xor_sync(0xffffffff, sq, off);
        if ((tid & 31) == 0) red[tid >> 5] = sq;
        __syncthreads();
        float nrm = sqrtf(red[0] + red[1]);
        lam = nrm;                        // ||G v|| -> lambda_max = sigma^2
        if (tid < R) v[tid] = s / nrm;
        __syncthreads();
    }
    if (tid == 0) g_sigma[bid] = sqrtf(lam);
}

// ---------------------------------------------------------------------------
// Kernel 2: 1x1-conv projections f, g, h with spectrally-normalized weights.
// ---------------------------------------------------------------------------
__global__ __launch_bounds__(256)
void proj_kernel(const float* __restrict__ x,
                 const float* __restrict__ Wq, const float* __restrict__ bq,
                 const float* __restrict__ Wk, const float* __restrict__ bk,
                 const float* __restrict__ Wv, const float* __restrict__ bv) {
    __shared__ float sWq[C8 * CC], sWk[C8 * CC], sWv[CC * CC];
    __shared__ float sbq[C8], sbk[C8], sbv[CC];

    const int tid = threadIdx.x;
    const float isq = 1.f / g_sigma[0];
    const float isk = 1.f / g_sigma[1];
    const float isv = 1.f / g_sigma[2];

    for (int e = tid; e < C8 * CC; e += 256) { sWq[e] = Wq[e] * isq; sWk[e] = Wk[e] * isk; }
    for (int e = tid; e < CC * CC; e += 256) { sWv[e] = Wv[e] * isv; }
    if (tid < C8) { sbq[tid] = bq[tid]; sbk[tid] = bk[tid]; }
    if (tid < CC) { sbv[tid] = bv[tid]; }
    __syncthreads();

    const int t = blockIdx.x * 256 + tid;
    const int b = t / NN;
    const int n = t % NN;

    float xr[CC];
    #pragma unroll
    for (int c = 0; c < CC; c++) xr[c] = x[(b * CC + c) * NN + n];

    #pragma unroll
    for (int o = 0; o < C8; o++) {
        float sf = sbq[o], sg = sbk[o];
        #pragma unroll
        for (int k = 0; k < CC; k++) {
            sf += sWq[o * CC + k] * xr[k];
            sg += sWk[o * CC + k] * xr[k];
        }
        g_f[(b * C8 + o) * NN + n] = sf;
        g_g[(b * C8 + o) * NN + n] = sg;
    }
    #pragma unroll 4
    for (int o = 0; o < CC; o++) {
        float s = sbv[o];
        #pragma unroll
        for (int k = 0; k < CC; k++) s += sWv[o * CC + k] * xr[k];
        g_h[(b * CC + o) * NN + n] = s;
    }
}

// ---------------------------------------------------------------------------
// Kernel 3: split-K flash attention, branchless subtile softmax + f32x2 math.
// Thread owns output position j; keys processed in subtiles of KT=8:
//   scores(8) -> tree max -> unconditional rescale (exp2(0)=1 no-op)
//   -> 8 independent MUFU exps -> PV rank-1 updates.
// grid = (72, B, SPLITS), 128 threads.
// ---------------------------------------------------------------------------
__global__ __launch_bounds__(128, 4)
void attn_kernel() {
    __shared__ float sK[TK][12];    // padded
    __shared__ float sV[TK][68];    // padded (272B rows, 16B aligned)

    const int b  = blockIdx.y;
    const int sp = blockIdx.z;
    const int j  = blockIdx.x * 128 + threadIdx.x;

    uint64_t q2[4];
    #pragma unroll
    for (int cc = 0; cc < 4; cc++)
        q2[cc] = pack2(g_g[(b * C8 + 2 * cc) * NN + j] * LOG2E,
                       g_g[(b * C8 + 2 * cc + 1) * NN + j] * LOG2E);

    float m = -1e30f, l = 0.f;
    uint64_t acc[32];
    #pragma unroll
    for (int c = 0; c < 32; c++) acc[c] = 0ull;

    const int i_beg = sp * KPS;
    for (int i0 = i_beg; i0 < i_beg + KPS; i0 += TK) {
        __syncthreads();
        #pragma unroll
        for (int e = threadIdx.x; e < TK * C8; e += 128) {
            int c = e >> 7, i = e & 127;
            sK[i][c] = g_f[(b * C8 + c) * NN + i0 + i];
        }
        #pragma unroll
        for (int e = threadIdx.x; e < TK * CC; e += 128) {
            int c = e >> 7, i = e & 127;
            sV[i][c] = g_h[(b * CC + c) * NN + i0 + i];
        }
        __syncthreads();

        for (int t = 0; t < TK; t += KT) {
            // --- scores for KT keys (log2 domain; q pre-scaled) ---
            float s[KT];
            #pragma unroll
            for (int u = 0; u < KT; u++) {
                const ulonglong2* kr = (const ulonglong2*)&sK[t + u][0];
                ulonglong2 k0 = kr[0];
                ulonglong2 k1 = kr[1];
                uint64_t s2 = fmul2(q2[0], k0.x);
                s2 = ffma2(q2[1], k0.y, s2);
                s2 = ffma2(q2[2], k1.x, s2);
                s2 = ffma2(q2[3], k1.y, s2);
                float se, so; unpack2(s2, se, so);
                s[u] = se + so;
            }
            // --- subtile max, unconditional rescale ---
            float tm = fmaxf(fmaxf(fmaxf(s[0], s[1]), fmaxf(s[2], s[3])),
                             fmaxf(fmaxf(s[4], s[5]), fmaxf(s[6], s[7])));
            float mn = fmaxf(m, tm);
            float sc = ex2(m - mn);        // exactly 1.0 when max unchanged
            m = mn;
            l *= sc;
            uint64_t sc2 = pack2(sc, sc);
            #pragma unroll
            for (int c = 0; c < 32; c++) acc[c] = fmul2(acc[c], sc2);
            // --- batched independent exps ---
            float p[KT];
            #pragma unroll
            for (int u = 0; u < KT; u++) p[u] = ex2(s[u] - m);
            l += ((p[0] + p[1]) + (p[2] + p[3])) + ((p[4] + p[5]) + (p[6] + p[7]));
            // --- PV rank-1 updates ---
            #pragma unroll
            for (int u = 0; u < KT; u++) {
                uint64_t p2 = pack2(p[u], p[u]);
                const ulonglong2* vr = (const ulonglong2*)&sV[t + u][0];
                #pragma unroll
                for (int c = 0; c < 16; c++) {
                    ulonglong2 vv = vr[c];
                    acc[2 * c]     = ffma2(p2, vv.x, acc[2 * c]);
                    acc[2 * c + 1] = ffma2(p2, vv.y, acc[2 * c + 1]);
                }
            }
        }
    }

    const int ps = (b * SPLITS + sp);
    g_pm[ps * NN + j] = m;
    g_pl[ps * NN + j] = l;
    #pragma unroll
    for (int c = 0; c < 32; c++) {
        float a0, a1; unpack2(acc[c], a0, a1);
        g_pacc[(ps * CC + 2 * c)     * NN + j] = a0;
        g_pacc[(ps * CC + 2 * c + 1) * NN + j] = a1;
    }
}

// ---------------------------------------------------------------------------
// Kernel 4: combine split partials, apply gamma + residual.
// ---------------------------------------------------------------------------
__global__ __launch_bounds__(256)
void reduce_kernel(const float* __restrict__ x,
                   const float* __restrict__ gamma,
                   float* __restrict__ out) {
    const int t = blockIdx.x * 256 + threadIdx.x;
    const int b = t / NN;
    const int j = t % NN;

    float ms[SPLITS], ls[SPLITS];
    float M = -1e30f;
    #pragma unroll
    for (int s = 0; s < SPLITS; s++) {
        ms[s] = g_pm[(b * SPLITS + s) * NN + j];
        ls[s] = g_pl[(b * SPLITS + s) * NN + j];
        M = fmaxf(M, ms[s]);
    }
    float w[SPLITS], L = 0.f;
    #pragma unroll
    for (int s = 0; s < SPLITS; s++) {
        w[s] = ex2(ms[s] - M);        // log2 domain
        L += ls[s] * w[s];
    }
    const float inv = gamma[0] / L;

    #pragma unroll 4
    for (int c = 0; c < CC; c++) {
        float a = 0.f;
        #pragma unroll
        for (int s = 0; s < SPLITS; s++)
            a += g_pacc[((b * SPLITS + s) * CC + c) * NN + j] * w[s];
        const int idx = (b * CC + c) * NN + j;
        out[idx] = a * inv + x[idx];
    }
}

// ---------------------------------------------------------------------------
extern "C" void kernel_launch(void* const* d_in, const int* in_sizes, int n_in,
                              void* d_out, int out_size) {
    const float* x     = (const float*)d_in[0];
    const float* Wq    = (const float*)d_in[1];
    const float* bq    = (const float*)d_in[2];
    const float* Wk    = (const float*)d_in[3];
    const float* bk    = (const float*)d_in[4];
    const float* Wv    = (const float*)d_in[5];
    const float* bv    = (const float*)d_in[6];
    const float* gamma = (const float*)d_in[7];
    float* out = (float*)d_out;

    sigma_kernel<<<3, 64>>>(Wq, Wk, Wv);
    proj_kernel<<<(BB * NN) / 256, 256>>>(x, Wq, bq, Wk, bk, Wv, bv);
    attn_kernel<<<dim3(NN / 128, BB, SPLITS), 128>>>();
    reduce_kernel<<<(BB * NN) / 256, 256>>>(x, gamma, out);
}

// round 8
// speedup vs baseline: 4.5328x; 1.7021x over previous
#include <cuda_runtime.h>
#include <cuda_fp16.h>
#include <math.h>
#include <stdint.h>

#define CC     64
#define C8     8
#define NN     9216
#define BB     2
#define SPLITS 4
#define KPS    (NN / SPLITS)    // 2304 keys per split
#define TK     128              // keys staged per smem tile
#define VPAD   72               // sVh row pitch in halves (144B: ldmatrix conflict-free)
#define LOG2E  1.44269504088896340736f

// Scratch (no allocations allowed in kernel_launch)
__device__ float        g_sigma[3];
__device__ unsigned int g_kmax2;                   // max ||f_i||^2 (bits of nonneg float)
__device__ float        g_f[BB * C8 * NN];         // keys    [B, 8, N] fp32
__device__ float        g_g[BB * C8 * NN];         // queries [B, 8, N] fp32
__device__ __half       g_ht[BB * NN * CC];        // values  [B, N, 64] fp16 (row-major)
__device__ float        g_pl[BB * SPLITS * NN];    // split partial denominators
__device__ float        g_pacc[BB * SPLITS * CC * NN];  // split partial numerators

// ---- packed f32x2 helpers (SASS FFMA2) ----
__device__ __forceinline__ uint64_t pack2(float lo, float hi) {
    uint64_t r; asm("mov.b64 %0, {%1, %2};" : "=l"(r) : "f"(lo), "f"(hi)); return r;
}
__device__ __forceinline__ uint64_t ffma2(uint64_t a, uint64_t b, uint64_t c) {
    uint64_t d; asm("fma.rn.f32x2 %0, %1, %2, %3;" : "=l"(d) : "l"(a), "l"(b), "l"(c)); return d;
}
__device__ __forceinline__ uint64_t fmul2(uint64_t a, uint64_t b) {
    uint64_t d; asm("mul.rn.f32x2 %0, %1, %2;" : "=l"(d) : "l"(a), "l"(b)); return d;
}
__device__ __forceinline__ void unpack2(uint64_t v, float& lo, float& hi) {
    asm("mov.b64 {%0, %1}, %2;" : "=f"(lo), "=f"(hi) : "l"(v));
}
__device__ __forceinline__ float ex2(float x) {
    float r; asm("ex2.approx.f32 %0, %1;" : "=f"(r) : "f"(x)); return r;
}
// d = {lo, hi} packed fp16x2  (PTX: first source -> high half)
__device__ __forceinline__ uint32_t cvt16x2(float hi, float lo) {
    uint32_t d; asm("cvt.rn.f16x2.f32 %0, %1, %2;" : "=r"(d) : "f"(hi), "f"(lo)); return d;
}
__device__ __forceinline__ void mma16816(float& d0, float& d1, float& d2, float& d3,
                                         uint32_t a0, uint32_t a1, uint32_t a2, uint32_t a3,
                                         uint32_t b0, uint32_t b1) {
    asm volatile("mma.sync.aligned.m16n8k16.row.col.f32.f16.f16.f32 "
                 "{%0,%1,%2,%3}, {%4,%5,%6,%7}, {%8,%9}, {%0,%1,%2,%3};"
                 : "+f"(d0), "+f"(d1), "+f"(d2), "+f"(d3)
                 : "r"(a0), "r"(a1), "r"(a2), "r"(a3), "r"(b0), "r"(b1));
}
__device__ __forceinline__ void ldmx4t(uint32_t& b0, uint32_t& b1, uint32_t& b2, uint32_t& b3,
                                       uint32_t smaddr) {
    asm volatile("ldmatrix.sync.aligned.m8n8.x4.trans.shared.b16 {%0,%1,%2,%3}, [%4];"
                 : "=r"(b0), "=r"(b1), "=r"(b2), "=r"(b3) : "r"(smaddr));
}

// ---------------------------------------------------------------------------
// Kernel 1: spectral norms via power iteration on Gram matrix G = W W^T.
// Also resets g_kmax2 for this launch (graph-replay safe: runs before proj).
// ---------------------------------------------------------------------------
__global__ __launch_bounds__(64)
void sigma_kernel(const float* __restrict__ Wq,
                  const float* __restrict__ Wk,
                  const float* __restrict__ Wv) {
    __shared__ float sW[64 * 64];
    __shared__ float v[64];
    __shared__ float red[2];
    const int bid = blockIdx.x;
    const int tid = threadIdx.x;
    if (bid == 0 && tid == 0) g_kmax2 = 0u;
    const float* W = (bid == 0) ? Wq : ((bid == 1) ? Wk : Wv);
    const int R = (bid == 2) ? 64 : 8;

    for (int e = tid; e < R * 64; e += 64) sW[e] = W[e];
    if (tid < R) v[tid] = 1.f;
    __syncthreads();

    float Gr[64];
    if (tid < R) {
        float wr[64];
        #pragma unroll
        for (int k = 0; k < 64; k++) wr[k] = sW[tid * 64 + k];
        for (int c = 0; c < R; c++) {
            float a[8];
            #pragma unroll
            for (int u = 0; u < 8; u++) a[u] = wr[u] * sW[c * 64 + u];
            #pragma unroll
            for (int k = 8; k < 64; k += 8)
                #pragma unroll
                for (int u = 0; u < 8; u++) a[u] += wr[k + u] * sW[c * 64 + k + u];
            Gr[c] = ((a[0] + a[1]) + (a[2] + a[3])) + ((a[4] + a[5]) + (a[6] + a[7]));
        }
    }
    __syncthreads();

    float lam = 1.f;
    for (int it = 0; it < 56; it++) {
        float s = 0.f;
        if (tid < R) {
            float a0 = 0.f, a1 = 0.f, a2 = 0.f, a3 = 0.f;
            for (int k = 0; k < R; k += 4) {
                a0 += Gr[k]     * v[k];
                a1 += Gr[k + 1] * v[k + 1];
                a2 += Gr[k + 2] * v[k + 2];
                a3 += Gr[k + 3] * v[k + 3];
            }
            s = (a0 + a1) + (a2 + a3);
        }
        float sq = (tid < R) ? s * s : 0.f;
        #pragma unroll
        for (int off = 16; off > 0; off >>= 1)
            sq += __shfl_xor_sync(0xffffffff, sq, off);
        if ((tid & 31) == 0) red[tid >> 5] = sq;
        __syncthreads();
        float nrm = sqrtf(red[0] + red[1]);
        lam = nrm;                         // ||G v|| -> sigma^2
        if (tid < R) v[tid] = s / nrm;
        __syncthreads();
    }
    if (tid == 0) g_sigma[bid] = sqrtf(lam);
}

// ---------------------------------------------------------------------------
// Kernel 2: projections. f,g fp32 [c][n]; h -> fp16 [n][c] (row-major for
// direct smem copy in attn). Also computes global max ||f||^2 (one atomic/block).
// ---------------------------------------------------------------------------
__global__ __launch_bounds__(256)
void proj_kernel(const float* __restrict__ x,
                 const float* __restrict__ Wq, const float* __restrict__ bq,
                 const float* __restrict__ Wk, const float* __restrict__ bk,
                 const float* __restrict__ Wv, const float* __restrict__ bv) {
    __shared__ float sWq[C8 * CC], sWk[C8 * CC], sWv[CC * CC];
    __shared__ float sbq[C8], sbk[C8], sbv[CC];
    __shared__ float swmax[8];

    const int tid = threadIdx.x;
    const float isq = 1.f / g_sigma[0];
    const float isk = 1.f / g_sigma[1];
    const float isv = 1.f / g_sigma[2];

    for (int e = tid; e < C8 * CC; e += 256) { sWq[e] = Wq[e] * isq; sWk[e] = Wk[e] * isk; }
    for (int e = tid; e < CC * CC; e += 256) { sWv[e] = Wv[e] * isv; }
    if (tid < C8) { sbq[tid] = bq[tid]; sbk[tid] = bk[tid]; }
    if (tid < CC) { sbv[tid] = bv[tid]; }
    __syncthreads();

    const int t = blockIdx.x * 256 + tid;
    const int b = t / NN;
    const int n = t % NN;

    float xr[CC];
    #pragma unroll
    for (int c = 0; c < CC; c++) xr[c] = x[(b * CC + c) * NN + n];

    float nf = 0.f;
    #pragma unroll
    for (int o = 0; o < C8; o++) {
        float sf = sbq[o], sg = sbk[o];
        #pragma unroll
        for (int k = 0; k < CC; k++) {
            sf += sWq[o * CC + k] * xr[k];
            sg += sWk[o * CC + k] * xr[k];
        }
        g_f[(b * C8 + o) * NN + n] = sf;   // keys
        g_g[(b * C8 + o) * NN + n] = sg;   // queries
        nf += sf * sf;
    }

    // block-reduce max ||f||^2, single atomic per block
    float wm = nf;
    #pragma unroll
    for (int off = 16; off > 0; off >>= 1)
        wm = fmaxf(wm, __shfl_xor_sync(0xffffffff, wm, off));
    if ((tid & 31) == 0) swmax[tid >> 5] = wm;
    __syncthreads();
    if (tid == 0) {
        float bm = swmax[0];
        #pragma unroll
        for (int w = 1; w < 8; w++) bm = fmaxf(bm, swmax[w]);
        atomicMax(&g_kmax2, __float_as_uint(bm));
    }

    // h in fp16, [n][c] row-major
    uint32_t* ht = (uint32_t*)&g_ht[(b * NN + n) * CC];
    #pragma unroll 4
    for (int o = 0; o < CC; o += 2) {
        float s0 = sbv[o], s1 = sbv[o + 1];
        #pragma unroll
        for (int k = 0; k < CC; k++) {
            s0 += sWv[o * CC + k] * xr[k];
            s1 += sWv[(o + 1) * CC + k] * xr[k];
        }
        ht[o >> 1] = cvt16x2(s1, s0);
    }
}

// ---------------------------------------------------------------------------
// Kernel 3: HMMA flash attention, fixed-M softmax (no online max/rescale).
// 128 threads = 4 warps; warp owns a 16-j tile (block: 64 j). Thread
// (gid=lane>>2, tig=lane&3) computes fragment-resident scores for
// j0=jt+gid, j1=j0+8 and keys iA=t+2tig{,+1}, iB=iA+8 via f32x2 SIMT QK,
// converts p to fp16 A-fragments, and accumulates O with m16n8k16 MMA
// against V B-fragments ldmatrix'd from smem. grid = (144, B, SPLITS).
// ---------------------------------------------------------------------------
__global__ __launch_bounds__(128, 3)
void attn_kernel() {
    __shared__ float  sKt[C8][TK + 4];     // keys fp32 [c][i]
    __shared__ __half sVh[TK][VPAD];       // values fp16 [i][c]

    const int b    = blockIdx.y;
    const int sp   = blockIdx.z;
    const int warp = threadIdx.x >> 5;
    const int lane = threadIdx.x & 31;
    const int gid  = lane >> 2, tig = lane & 3;
    const int jt   = blockIdx.x * 64 + warp * 16;
    const int j0   = jt + gid, j1 = j0 + 8;

    // queries for my two fragment rows; fixed per-row log2-domain bound M
    float q0[C8], q1[C8];
    float nq0 = 0.f, nq1 = 0.f;
    #pragma unroll
    for (int c = 0; c < C8; c++) {
        q0[c] = g_g[(b * C8 + c) * NN + j0]; nq0 += q0[c] * q0[c];
        q1[c] = g_g[(b * C8 + c) * NN + j1]; nq1 += q1[c] * q1[c];
    }
    const float kmax = sqrtf(__uint_as_float(g_kmax2));
    const float M0 = sqrtf(nq0) * kmax * LOG2E - 10.f;
    const float M1 = sqrtf(nq1) * kmax * LOG2E - 10.f;
    uint64_t q2A[C8], q2B[C8];
    #pragma unroll
    for (int c = 0; c < C8; c++) {
        float a = q0[c] * LOG2E, d = q1[c] * LOG2E;
        q2A[c] = pack2(a, a);
        q2B[c] = pack2(d, d);
    }

    float acc[32];
    #pragma unroll
    for (int c = 0; c < 32; c++) acc[c] = 0.f;
    float l0 = 0.f, l1 = 0.f;

    const uint32_t sVh_base = (uint32_t)__cvta_generic_to_shared(&sVh[0][0]);
    // ldmatrix address components (fixed per thread): row-in-tile + k-half, n-half
    const int lrow = (lane & 7) + ((lane >> 3) & 1) * 8;   // key row within 16-chunk
    const int lcol = (lane >> 4) * 8;                      // n-col offset within 16-group

    const int i_beg = sp * KPS;
    for (int i0 = i_beg; i0 < i_beg + KPS; i0 += TK) {
        __syncthreads();
        // stage K [c][i] fp32
        #pragma unroll
        for (int r = 0; r < 2; r++) {
            int e = r * 128 + threadIdx.x;
            int c = e >> 5, i4 = e & 31;
            float4 kv = *(const float4*)&g_f[(b * C8 + c) * NN + i0 + i4 * 4];
            *(float4*)&sKt[c][i4 * 4] = kv;
        }
        // stage V rows (already fp16 [i][c] in gmem): 128B straight copy
        {
            const uint4* src = (const uint4*)&g_ht[(b * NN + i0 + threadIdx.x) * CC];
            uint4* dst = (uint4*)&sVh[threadIdx.x][0];
            #pragma unroll
            for (int r = 0; r < 8; r++) dst[r] = src[r];
        }
        __syncthreads();

        for (int t = 0; t < TK; t += 16) {
            const int iA = t + 2 * tig, iB = iA + 8;
            // ---- scores: 4 fragment pairs, f32x2 ----
            uint64_t kA = *(const uint64_t*)&sKt[0][iA];
            uint64_t kB = *(const uint64_t*)&sKt[0][iB];
            uint64_t sA0 = fmul2(q2A[0], kA), sA1 = fmul2(q2B[0], kA);
            uint64_t sB0 = fmul2(q2A[0], kB), sB1 = fmul2(q2B[0], kB);
            #pragma unroll
            for (int c = 1; c < C8; c++) {
                kA = *(const uint64_t*)&sKt[c][iA];
                kB = *(const uint64_t*)&sKt[c][iB];
                sA0 = ffma2(q2A[c], kA, sA0);
                sA1 = ffma2(q2B[c], kA, sA1);
                sB0 = ffma2(q2A[c], kB, sB0);
                sB1 = ffma2(q2B[c], kB, sB1);
            }
            float sA0l, sA0h, sA1l, sA1h, sB0l, sB0h, sB1l, sB1h;
            unpack2(sA0, sA0l, sA0h); unpack2(sA1, sA1l, sA1h);
            unpack2(sB0, sB0l, sB0h); unpack2(sB1, sB1l, sB1h);
            // ---- p = 2^(s - M): fixed bound, no rescale ----
            float p00 = ex2(sA0l - M0), p01 = ex2(sA0h - M0);
            float p02 = ex2(sB0l - M0), p03 = ex2(sB0h - M0);
            float p10 = ex2(sA1l - M1), p11 = ex2(sA1h - M1);
            float p12 = ex2(sB1l - M1), p13 = ex2(sB1h - M1);
            l0 += (p00 + p01) + (p02 + p03);
            l1 += (p10 + p11) + (p12 + p13);
            // A fragment regs: {(j0,iA),(j1,iA),(j0,iB),(j1,iB)}
            uint32_t a0 = cvt16x2(p01, p00);
            uint32_t a1 = cvt16x2(p11, p10);
            uint32_t a2 = cvt16x2(p03, p02);
            uint32_t a3 = cvt16x2(p13, p12);
            // ---- V fragments + MMA over 8 n-tiles ----
            uint32_t rowaddr = sVh_base + (uint32_t)((t + lrow) * (VPAD * 2) + lcol * 2);
            #pragma unroll
            for (int g = 0; g < 4; g++) {
                uint32_t b0, b1, b2, b3;
                ldmx4t(b0, b1, b2, b3, rowaddr + (uint32_t)(g * 32));
                float* d = &acc[g * 8];
                mma16816(d[0], d[1], d[2], d[3], a0, a1, a2, a3, b0, b1);
                mma16816(d[4], d[5], d[6], d[7], a0, a1, a2, a3, b2, b3);
            }
        }
    }

    // quad-reduce denominators (partial over this thread's i columns)
    l0 += __shfl_xor_sync(0xffffffff, l0, 1);
    l0 += __shfl_xor_sync(0xffffffff, l0, 2);
    l1 += __shfl_xor_sync(0xffffffff, l1, 1);
    l1 += __shfl_xor_sync(0xffffffff, l1, 2);

    const int ps = b * SPLITS + sp;
    if (tig == 0) {
        g_pl[ps * NN + j0] = l0;
        g_pl[ps * NN + j1] = l1;
    }
    #pragma unroll
    for (int nt = 0; nt < 8; nt++) {
        const int c = nt * 8 + 2 * tig;
        g_pacc[(ps * CC + c)     * NN + j0] = acc[nt * 4 + 0];
        g_pacc[(ps * CC + c + 1) * NN + j0] = acc[nt * 4 + 1];
        g_pacc[(ps * CC + c)     * NN + j1] = acc[nt * 4 + 2];
        g_pacc[(ps * CC + c + 1) * NN + j1] = acc[nt * 4 + 3];
    }
}

// ---------------------------------------------------------------------------
// Kernel 4: combine split partials (plain sums — common fixed M), residual.
// ---------------------------------------------------------------------------
__global__ __launch_bounds__(256)
void reduce_kernel(const float* __restrict__ x,
                   const float* __restrict__ gamma,
                   float* __restrict__ out) {
    const int t = blockIdx.x * 256 + threadIdx.x;
    const int b = t / NN;
    const int j = t % NN;

    float L = 0.f;
    #pragma unroll
    for (int s = 0; s < SPLITS; s++) L += g_pl[(b * SPLITS + s) * NN + j];
    const float inv = gamma[0] / L;

    #pragma unroll 4
    for (int c = 0; c < CC; c++) {
        float a = 0.f;
        #pragma unroll
        for (int s = 0; s < SPLITS; s++)
            a += g_pacc[((b * SPLITS + s) * CC + c) * NN + j];
        const int idx = (b * CC + c) * NN + j;
        out[idx] = a * inv + x[idx];
    }
}

// ---------------------------------------------------------------------------
extern "C" void kernel_launch(void* const* d_in, const int* in_sizes, int n_in,
                              void* d_out, int out_size) {
    const float* x     = (const float*)d_in[0];
    const float* Wq    = (const float*)d_in[1];
    const float* bq    = (const float*)d_in[2];
    const float* Wk    = (const float*)d_in[3];
    const float* bk    = (const float*)d_in[4];
    const float* Wv    = (const float*)d_in[5];
    const float* bv    = (const float*)d_in[6];
    const float* gamma = (const float*)d_in[7];
    float* out = (float*)d_out;

    sigma_kernel<<<3, 64>>>(Wq, Wk, Wv);
    proj_kernel<<<(BB * NN) / 256, 256>>>(x, Wq, bq, Wk, bk, Wv, bv);
    attn_kernel<<<dim3(NN / 64, BB, SPLITS), 128>>>();
    reduce_kernel<<<(BB * NN) / 256, 256>>>(x, gamma, out);
}

// round 11
// speedup vs baseline: 8.5479x; 1.8858x over previous
#include <cuda_runtime.h>
#include <cuda_fp16.h>
#include <math.h>
#include <stdint.h>

#define CC     64
#define C8     8
#define NN     9216
#define BB     2
#define SPLITS 4
#define KPS    (NN / SPLITS)    // 2304 keys per split
#define TK     128              // keys staged per smem tile
#define NT     (KPS / TK)       // 18 tiles per block
#define VPAD   72               // sVh row pitch in halves (144B, 16B-aligned, ldmatrix conflict-free)
#define LOG2E  1.44269504088896340736f

// Scratch (no allocations allowed in kernel_launch)
__device__ float        g_sigma[3];
__device__ unsigned int g_kmax2;                   // max ||f_i||^2 (bits of nonneg float)
__device__ float        g_f[BB * C8 * NN];         // keys    [B, 8, N] fp32
__device__ float        g_g[BB * C8 * NN];         // queries [B, 8, N] fp32
__device__ __half       g_ht[BB * NN * CC];        // values  [B, N, 64] fp16 (row-major)
__device__ float        g_pl[BB * SPLITS * NN];    // split partial denominators
__device__ float        g_pacc[BB * SPLITS * CC * NN];  // split partial numerators

// ---- packed f32x2 helpers (SASS FFMA2) ----
__device__ __forceinline__ uint64_t pack2(float lo, float hi) {
    uint64_t r; asm("mov.b64 %0, {%1, %2};" : "=l"(r) : "f"(lo), "f"(hi)); return r;
}
__device__ __forceinline__ uint64_t ffma2(uint64_t a, uint64_t b, uint64_t c) {
    uint64_t d; asm("fma.rn.f32x2 %0, %1, %2, %3;" : "=l"(d) : "l"(a), "l"(b), "l"(c)); return d;
}
__device__ __forceinline__ void unpack2(uint64_t v, float& lo, float& hi) {
    asm("mov.b64 {%0, %1}, %2;" : "=f"(lo), "=f"(hi) : "l"(v));
}
__device__ __forceinline__ float ex2(float x) {
    float r; asm("ex2.approx.f32 %0, %1;" : "=f"(r) : "f"(x)); return r;
}
// d = {lo, hi} packed fp16x2  (PTX: first source -> high half)
__device__ __forceinline__ uint32_t cvt16x2(float hi, float lo) {
    uint32_t d; asm("cvt.rn.f16x2.f32 %0, %1, %2;" : "=r"(d) : "f"(hi), "f"(lo)); return d;
}
__device__ __forceinline__ void mma16816(float& d0, float& d1, float& d2, float& d3,
                                         uint32_t a0, uint32_t a1, uint32_t a2, uint32_t a3,
                                         uint32_t b0, uint32_t b1) {
    asm volatile("mma.sync.aligned.m16n8k16.row.col.f32.f16.f16.f32 "
                 "{%0,%1,%2,%3}, {%4,%5,%6,%7}, {%8,%9}, {%0,%1,%2,%3};"
                 : "+f"(d0), "+f"(d1), "+f"(d2), "+f"(d3)
                 : "r"(a0), "r"(a1), "r"(a2), "r"(a3), "r"(b0), "r"(b1));
}
__device__ __forceinline__ void ldmx4t(uint32_t& b0, uint32_t& b1, uint32_t& b2, uint32_t& b3,
                                       uint32_t smaddr) {
    asm volatile("ldmatrix.sync.aligned.m8n8.x4.trans.shared.b16 {%0,%1,%2,%3}, [%4];"
                 : "=r"(b0), "=r"(b1), "=r"(b2), "=r"(b3) : "r"(smaddr));
}
// ---- cp.async (LDGSTS) ----
__device__ __forceinline__ void cpa16(uint32_t dst, const void* src) {
    asm volatile("cp.async.cg.shared.global [%0], [%1], 16;" :: "r"(dst), "l"(src));
}
__device__ __forceinline__ void cpa_commit() {
    asm volatile("cp.async.commit_group;");
}
template <int N>
__device__ __forceinline__ void cpa_wait() {
    asm volatile("cp.async.wait_group %0;" :: "n"(N));
}

// ---------------------------------------------------------------------------
// Kernel 1: spectral norms via power iteration on Gram matrix G = W W^T.
// Also resets g_kmax2 for this launch.
// ---------------------------------------------------------------------------
__global__ __launch_bounds__(64)
void sigma_kernel(const float* __restrict__ Wq,
                  const float* __restrict__ Wk,
                  const float* __restrict__ Wv) {
    __shared__ float sW[64 * 64];
    __shared__ float v[64];
    __shared__ float red[2];
    const int bid = blockIdx.x;
    const int tid = threadIdx.x;
    if (bid == 0 && tid == 0) g_kmax2 = 0u;
    const float* W = (bid == 0) ? Wq : ((bid == 1) ? Wk : Wv);
    const int R = (bid == 2) ? 64 : 8;

    for (int e = tid; e < R * 64; e += 64) sW[e] = W[e];
    if (tid < R) v[tid] = 1.f;
    __syncthreads();

    float Gr[64];
    if (tid < R) {
        float wr[64];
        #pragma unroll
        for (int k = 0; k < 64; k++) wr[k] = sW[tid * 64 + k];
        for (int c = 0; c < R; c++) {
            float a[8];
            #pragma unroll
            for (int u = 0; u < 8; u++) a[u] = wr[u] * sW[c * 64 + u];
            #pragma unroll
            for (int k = 8; k < 64; k += 8)
                #pragma unroll
                for (int u = 0; u < 8; u++) a[u] += wr[k + u] * sW[c * 64 + k + u];
            Gr[c] = ((a[0] + a[1]) + (a[2] + a[3])) + ((a[4] + a[5]) + (a[6] + a[7]));
        }
    }
    __syncthreads();

    float lam = 1.f;
    for (int it = 0; it < 56; it++) {
        float s = 0.f;
        if (tid < R) {
            if (R == 8) {
                float2 v0 = *(const float2*)&v[0], v1 = *(const float2*)&v[2];
                float2 v2 = *(const float2*)&v[4], v3 = *(const float2*)&v[6];
                s = ((Gr[0] * v0.x + Gr[1] * v0.y) + (Gr[2] * v1.x + Gr[3] * v1.y))
                  + ((Gr[4] * v2.x + Gr[5] * v2.y) + (Gr[6] * v3.x + Gr[7] * v3.y));
            } else {
                // MLP: 16 independent LDS.128 then FMA trees
                float a0 = 0.f, a1 = 0.f, a2 = 0.f, a3 = 0.f;
                #pragma unroll
                for (int k4 = 0; k4 < 16; k4++) {
                    float4 vv = *(const float4*)&v[k4 * 4];
                    a0 += Gr[k4 * 4]     * vv.x;
                    a1 += Gr[k4 * 4 + 1] * vv.y;
                    a2 += Gr[k4 * 4 + 2] * vv.z;
                    a3 += Gr[k4 * 4 + 3] * vv.w;
                }
                s = (a0 + a1) + (a2 + a3);
            }
        }
        float sq = (tid < R) ? s * s : 0.f;
        #pragma unroll
        for (int off = 16; off > 0; off >>= 1)
            sq += __shfl_xor_sync(0xffffffff, sq, off);
        if ((tid & 31) == 0) red[tid >> 5] = sq;
        __syncthreads();
        float nrm = sqrtf(red[0] + red[1]);
        lam = nrm;                         // ||G v|| -> sigma^2
        if (tid < R) v[tid] = s / nrm;
        __syncthreads();
    }
    if (tid == 0) g_sigma[bid] = sqrtf(lam);
}

// ---------------------------------------------------------------------------
// Kernel 2: projections. f,g fp32 [c][n]; h -> fp16 [n][c]. Also computes
// global max ||f||^2 (one atomic per block).
// ---------------------------------------------------------------------------
__global__ __launch_bounds__(256)
void proj_kernel(const float* __restrict__ x,
                 const float* __restrict__ Wq, const float* __restrict__ bq,
                 const float* __restrict__ Wk, const float* __restrict__ bk,
                 const float* __restrict__ Wv, const float* __restrict__ bv) {
    __shared__ float sWq[C8 * CC], sWk[C8 * CC], sWv[CC * CC];
    __shared__ float sbq[C8], sbk[C8], sbv[CC];
    __shared__ float swmax[8];

    const int tid = threadIdx.x;
    const float isq = 1.f / g_sigma[0];
    const float isk = 1.f / g_sigma[1];
    const float isv = 1.f / g_sigma[2];

    for (int e = tid; e < C8 * CC; e += 256) { sWq[e] = Wq[e] * isq; sWk[e] = Wk[e] * isk; }
    for (int e = tid; e < CC * CC; e += 256) { sWv[e] = Wv[e] * isv; }
    if (tid < C8) { sbq[tid] = bq[tid]; sbk[tid] = bk[tid]; }
    if (tid < CC) { sbv[tid] = bv[tid]; }
    __syncthreads();

    const int t = blockIdx.x * 256 + tid;
    const int b = t / NN;
    const int n = t % NN;

    float xr[CC];
    #pragma unroll
    for (int c = 0; c < CC; c++) xr[c] = x[(b * CC + c) * NN + n];

    float nf = 0.f;
    #pragma unroll
    for (int o = 0; o < C8; o++) {
        float sf = sbq[o], sg = sbk[o];
        #pragma unroll
        for (int k = 0; k < CC; k++) {
            sf += sWq[o * CC + k] * xr[k];
            sg += sWk[o * CC + k] * xr[k];
        }
        g_f[(b * C8 + o) * NN + n] = sf;   // keys
        g_g[(b * C8 + o) * NN + n] = sg;   // queries
        nf += sf * sf;
    }

    float wm = nf;
    #pragma unroll
    for (int off = 16; off > 0; off >>= 1)
        wm = fmaxf(wm, __shfl_xor_sync(0xffffffff, wm, off));
    if ((tid & 31) == 0) swmax[tid >> 5] = wm;
    __syncthreads();
    if (tid == 0) {
        float bm = swmax[0];
        #pragma unroll
        for (int w = 1; w < 8; w++) bm = fmaxf(bm, swmax[w]);
        atomicMax(&g_kmax2, __float_as_uint(bm));
    }

    uint32_t* ht = (uint32_t*)&g_ht[(b * NN + n) * CC];
    #pragma unroll 4
    for (int o = 0; o < CC; o += 2) {
        float s0 = sbv[o], s1 = sbv[o + 1];
        #pragma unroll
        for (int k = 0; k < CC; k++) {
            s0 += sWv[o * CC + k] * xr[k];
            s1 += sWv[(o + 1) * CC + k] * xr[k];
        }
        ht[o >> 1] = cvt16x2(s1, s0);
    }
}

// ---------------------------------------------------------------------------
// Kernel 3: HMMA flash attention, fixed-M softmax, cp.async double-buffered.
// 4 warps; warp owns a 16-j tile. Per 16-key step: fragment-resident f32x2
// QK (accumulator pre-seeded with -M), 8 MUFU exps, p->fp16 A fragments,
// 8 m16n8k16 MMAs vs ldmatrix'd V. grid = (144, B, SPLITS).
// ---------------------------------------------------------------------------
__global__ __launch_bounds__(128, 4)
void attn_kernel() {
    __shared__ float  sKt[2][C8][TK];      // keys fp32 [stage][c][i]
    __shared__ __half sVh[2][TK][VPAD];    // values fp16 [stage][i][c]

    const int b    = blockIdx.y;
    const int sp   = blockIdx.z;
    const int tid  = threadIdx.x;
    const int warp = tid >> 5;
    const int lane = tid & 31;
    const int gid  = lane >> 2, tig = lane & 3;
    const int jt   = blockIdx.x * 64 + warp * 16;
    const int j0   = jt + gid, j1 = j0 + 8;

    // queries + fixed per-row log2-domain bound M (Cauchy-Schwarz)
    float q0[C8], q1[C8];
    float nq0 = 0.f, nq1 = 0.f;
    #pragma unroll
    for (int c = 0; c < C8; c++) {
        q0[c] = g_g[(b * C8 + c) * NN + j0]; nq0 += q0[c] * q0[c];
        q1[c] = g_g[(b * C8 + c) * NN + j1]; nq1 += q1[c] * q1[c];
    }
    const float kmax = sqrtf(__uint_as_float(g_kmax2));
    const float M0 = sqrtf(nq0) * kmax * LOG2E - 10.f;
    const float M1 = sqrtf(nq1) * kmax * LOG2E - 10.f;
    const uint64_t M0n = pack2(-M0, -M0);
    const uint64_t M1n = pack2(-M1, -M1);
    uint64_t q2A[C8], q2B[C8];
    #pragma unroll
    for (int c = 0; c < C8; c++) {
        float a = q0[c] * LOG2E, d = q1[c] * LOG2E;
        q2A[c] = pack2(a, a);
        q2B[c] = pack2(d, d);
    }

    float acc[32];
    #pragma unroll
    for (int c = 0; c < 32; c++) acc[c] = 0.f;
    float l0 = 0.f, l1 = 0.f;

    const uint32_t skt_base = (uint32_t)__cvta_generic_to_shared(&sKt[0][0][0]);
    const uint32_t svh_base = (uint32_t)__cvta_generic_to_shared(&sVh[0][0][0]);
    const int lrow = (lane & 7) + ((lane >> 3) & 1) * 8;
    const int lcol = (lane >> 4) * 8;

    const int i_beg = sp * KPS;

    // prefetch helper (uniform across block)
    auto prefetch = [&](int tt, int s) {
        const int i0 = i_beg + tt * TK;
        #pragma unroll
        for (int r = 0; r < 2; r++) {
            int e = r * 128 + tid;
            int c = e >> 5, w = e & 31;       // 16B chunk within K row
            cpa16(skt_base + (uint32_t)(((s * C8 + c) * TK + w * 4) * 4),
                  &g_f[(b * C8 + c) * NN + i0 + w * 4]);
        }
        const __half* vsrc = &g_ht[(b * NN + i0 + tid) * CC];
        const uint32_t vdst = svh_base + (uint32_t)(((s * TK + tid) * VPAD) * 2);
        #pragma unroll
        for (int r = 0; r < 8; r++)
            cpa16(vdst + (uint32_t)(r * 16), vsrc + r * 8);
    };

    prefetch(0, 0);
    cpa_commit();

    for (int tt = 0; tt < NT; tt++) {
        const int s = tt & 1;
        cpa_wait<0>();
        __syncthreads();
        if (tt + 1 < NT) {
            prefetch(tt + 1, s ^ 1);
            cpa_commit();
        }

        const uint32_t svh_s = svh_base + (uint32_t)(s * TK * VPAD * 2);
        for (int t = 0; t < TK; t += 16) {
            const int iA = t + 2 * tig, iB = iA + 8;
            // ---- scores (accumulator pre-seeded with -M) ----
            uint64_t kA = *(const uint64_t*)&sKt[s][0][iA];
            uint64_t kB = *(const uint64_t*)&sKt[s][0][iB];
            uint64_t sA0 = ffma2(q2A[0], kA, M0n), sA1 = ffma2(q2B[0], kA, M1n);
            uint64_t sB0 = ffma2(q2A[0], kB, M0n), sB1 = ffma2(q2B[0], kB, M1n);
            #pragma unroll
            for (int c = 1; c < C8; c++) {
                kA = *(const uint64_t*)&sKt[s][c][iA];
                kB = *(const uint64_t*)&sKt[s][c][iB];
                sA0 = ffma2(q2A[c], kA, sA0);
                sA1 = ffma2(q2B[c], kA, sA1);
                sB0 = ffma2(q2A[c], kB, sB0);
                sB1 = ffma2(q2B[c], kB, sB1);
            }
            float sA0l, sA0h, sA1l, sA1h, sB0l, sB0h, sB1l, sB1h;
            unpack2(sA0, sA0l, sA0h); unpack2(sA1, sA1l, sA1h);
            unpack2(sB0, sB0l, sB0h); unpack2(sB1, sB1l, sB1h);
            // ---- p = 2^(s-M), independent MUFUs ----
            float p00 = ex2(sA0l), p01 = ex2(sA0h);
            float p02 = ex2(sB0l), p03 = ex2(sB0h);
            float p10 = ex2(sA1l), p11 = ex2(sA1h);
            float p12 = ex2(sB1l), p13 = ex2(sB1h);
            l0 += (p00 + p01) + (p02 + p03);
            l1 += (p10 + p11) + (p12 + p13);
            uint32_t a0 = cvt16x2(p01, p00);
            uint32_t a1 = cvt16x2(p11, p10);
            uint32_t a2 = cvt16x2(p03, p02);
            uint32_t a3 = cvt16x2(p13, p12);
            // ---- V fragments + MMAs ----
            uint32_t rowaddr = svh_s + (uint32_t)((t + lrow) * (VPAD * 2) + lcol * 2);
            #pragma unroll
            for (int g = 0; g < 4; g++) {
                uint32_t b0, b1, b2, b3;
                ldmx4t(b0, b1, b2, b3, rowaddr + (uint32_t)(g * 32));
                float* d = &acc[g * 8];
                mma16816(d[0], d[1], d[2], d[3], a0, a1, a2, a3, b0, b1);
                mma16816(d[4], d[5], d[6], d[7], a0, a1, a2, a3, b2, b3);
            }
        }
        __syncthreads();   // all warps done with stage s before it is refilled
    }

    l0 += __shfl_xor_sync(0xffffffff, l0, 1);
    l0 += __shfl_xor_sync(0xffffffff, l0, 2);
    l1 += __shfl_xor_sync(0xffffffff, l1, 1);
    l1 += __shfl_xor_sync(0xffffffff, l1, 2);

    const int ps = b * SPLITS + sp;
    if (tig == 0) {
        g_pl[ps * NN + j0] = l0;
        g_pl[ps * NN + j1] = l1;
    }
    #pragma unroll
    for (int nt = 0; nt < 8; nt++) {
        const int c = nt * 8 + 2 * tig;
        g_pacc[(ps * CC + c)     * NN + j0] = acc[nt * 4 + 0];
        g_pacc[(ps * CC + c + 1) * NN + j0] = acc[nt * 4 + 1];
        g_pacc[(ps * CC + c)     * NN + j1] = acc[nt * 4 + 2];
        g_pacc[(ps * CC + c + 1) * NN + j1] = acc[nt * 4 + 3];
    }
}

// ---------------------------------------------------------------------------
// Kernel 4: combine split partials (plain sums), residual. Parallel over
// channel quarters: grid (72, 4).
// ---------------------------------------------------------------------------
__global__ __launch_bounds__(256)
void reduce_kernel(const float* __restrict__ x,
                   const float* __restrict__ gamma,
                   float* __restrict__ out) {
    const int t  = blockIdx.x * 256 + threadIdx.x;
    const int b  = t / NN;
    const int j  = t % NN;
    const int c0 = blockIdx.y * 16;

    float L = 0.f;
    #pragma unroll
    for (int s = 0; s < SPLITS; s++) L += g_pl[(b * SPLITS + s) * NN + j];
    const float inv = gamma[0] / L;

    #pragma unroll
    for (int c = c0; c < c0 + 16; c++) {
        float a = 0.f;
        #pragma unroll
        for (int s = 0; s < SPLITS; s++)
            a += g_pacc[((b * SPLITS + s) * CC + c) * NN + j];
        const int idx = (b * CC + c) * NN + j;
        out[idx] = a * inv + x[idx];
    }
}

// ---------------------------------------------------------------------------
extern "C" void kernel_launch(void* const* d_in, const int* in_sizes, int n_in,
                              void* d_out, int out_size) {
    const float* x     = (const float*)d_in[0];
    const float* Wq    = (const float*)d_in[1];
    const float* bq    = (const float*)d_in[2];
    const float* Wk    = (const float*)d_in[3];
    const float* bk    = (const float*)d_in[4];
    const float* Wv    = (const float*)d_in[5];
    const float* bv    = (const float*)d_in[6];
    const float* gamma = (const float*)d_in[7];
    float* out = (float*)d_out;

    sigma_kernel<<<3, 64>>>(Wq, Wk, Wv);
    proj_kernel<<<(BB * NN) / 256, 256>>>(x, Wq, bq, Wk, bk, Wv, bv);
    attn_kernel<<<dim3(NN / 64, BB, SPLITS), 128>>>();
    reduce_kernel<<<dim3((BB * NN) / 256, 4), 256>>>(x, gamma, out);
}

// round 12
// speedup vs baseline: 8.7700x; 1.0260x over previous
#include <cuda_runtime.h>
#include <cuda_fp16.h>
#include <math.h>
#include <stdint.h>

#define CC     64
#define C8     8
#define NN     9216
#define BB     2
#define SPLITS 4
#define KPS    (NN / SPLITS)    // 2304 keys per split
#define TK     128              // keys staged per smem tile
#define NT     (KPS / TK)       // 18 tiles per block
#define VPAD   72               // sVh row pitch in halves (144B, 16B-aligned, ldmatrix conflict-free)
#define LOG2E  1.44269504088896340736f

// Scratch (no allocations allowed in kernel_launch)
__device__ float        g_sigma[3];
__device__ unsigned int g_kmax2;                   // max ||f_i||^2 (bits of nonneg float)
__device__ float        g_f[BB * C8 * NN];         // keys    [B, 8, N] fp32
__device__ float        g_g[BB * C8 * NN];         // queries [B, 8, N] fp32
__device__ __half       g_ht[BB * NN * CC];        // values  [B, N, 64] fp16 (row-major)
__device__ float        g_pl[BB * SPLITS * NN];    // split partial denominators
__device__ float        g_pacc[BB * SPLITS * CC * NN];  // split partial numerators

// ---- packed f32x2 helpers (SASS FFMA2) ----
__device__ __forceinline__ uint64_t pack2(float lo, float hi) {
    uint64_t r; asm("mov.b64 %0, {%1, %2};" : "=l"(r) : "f"(lo), "f"(hi)); return r;
}
__device__ __forceinline__ uint64_t ffma2(uint64_t a, uint64_t b, uint64_t c) {
    uint64_t d; asm("fma.rn.f32x2 %0, %1, %2, %3;" : "=l"(d) : "l"(a), "l"(b), "l"(c)); return d;
}
__device__ __forceinline__ void unpack2(uint64_t v, float& lo, float& hi) {
    asm("mov.b64 {%0, %1}, %2;" : "=f"(lo), "=f"(hi) : "l"(v));
}
__device__ __forceinline__ float ex2(float x) {
    float r; asm("ex2.approx.f32 %0, %1;" : "=f"(r) : "f"(x)); return r;
}
// d = {lo, hi} packed fp16x2  (PTX: first source -> high half)
__device__ __forceinline__ uint32_t cvt16x2(float hi, float lo) {
    uint32_t d; asm("cvt.rn.f16x2.f32 %0, %1, %2;" : "=r"(d) : "f"(hi), "f"(lo)); return d;
}
__device__ __forceinline__ void mma16816(float& d0, float& d1, float& d2, float& d3,
                                         uint32_t a0, uint32_t a1, uint32_t a2, uint32_t a3,
                                         uint32_t b0, uint32_t b1) {
    asm volatile("mma.sync.aligned.m16n8k16.row.col.f32.f16.f16.f32 "
                 "{%0,%1,%2,%3}, {%4,%5,%6,%7}, {%8,%9}, {%0,%1,%2,%3};"
                 : "+f"(d0), "+f"(d1), "+f"(d2), "+f"(d3)
                 : "r"(a0), "r"(a1), "r"(a2), "r"(a3), "r"(b0), "r"(b1));
}
__device__ __forceinline__ void ldmx4t(uint32_t& b0, uint32_t& b1, uint32_t& b2, uint32_t& b3,
                                       uint32_t smaddr) {
    asm volatile("ldmatrix.sync.aligned.m8n8.x4.trans.shared.b16 {%0,%1,%2,%3}, [%4];"
                 : "=r"(b0), "=r"(b1), "=r"(b2), "=r"(b3) : "r"(smaddr));
}
// ---- cp.async (LDGSTS) ----
__device__ __forceinline__ void cpa16(uint32_t dst, const void* src) {
    asm volatile("cp.async.cg.shared.global [%0], [%1], 16;" :: "r"(dst), "l"(src));
}
__device__ __forceinline__ void cpa_commit() {
    asm volatile("cp.async.commit_group;");
}
template <int N>
__device__ __forceinline__ void cpa_wait() {
    asm volatile("cp.async.wait_group %0;" :: "n"(N));
}

// ---------------------------------------------------------------------------
// Kernel 1: spectral norms via power iteration on Gram matrix G = W W^T.
// FFMA2-packed Gram build. Also resets g_kmax2 for this launch.
// ---------------------------------------------------------------------------
__global__ __launch_bounds__(64)
void sigma_kernel(const float* __restrict__ Wq,
                  const float* __restrict__ Wk,
                  const float* __restrict__ Wv) {
    __shared__ float sW[64 * 64];
    __shared__ float v[64];
    __shared__ float red[2];
    const int bid = blockIdx.x;
    const int tid = threadIdx.x;
    if (bid == 0 && tid == 0) g_kmax2 = 0u;
    const float* W = (bid == 0) ? Wq : ((bid == 1) ? Wk : Wv);
    const int R = (bid == 2) ? 64 : 8;

    for (int e = tid; e < R * 64; e += 64) sW[e] = W[e];
    if (tid < R) v[tid] = 1.f;
    __syncthreads();

    float Gr[64];
    if (tid < R) {
        uint64_t w2[32];
        const uint64_t* wrp = (const uint64_t*)&sW[tid * 64];
        #pragma unroll
        for (int i = 0; i < 32; i++) w2[i] = wrp[i];
        for (int c = 0; c < R; c++) {
            const uint64_t* wcp = (const uint64_t*)&sW[c * 64];   // broadcast
            uint64_t a0 = 0ull, a1 = 0ull, a2 = 0ull, a3 = 0ull;
            #pragma unroll
            for (int kk = 0; kk < 32; kk += 4) {
                a0 = ffma2(w2[kk],     wcp[kk],     a0);
                a1 = ffma2(w2[kk + 1], wcp[kk + 1], a1);
                a2 = ffma2(w2[kk + 2], wcp[kk + 2], a2);
                a3 = ffma2(w2[kk + 3], wcp[kk + 3], a3);
            }
            float x0, x1, y0, y1, z0, z1, u0, u1;
            unpack2(a0, x0, x1); unpack2(a1, y0, y1);
            unpack2(a2, z0, z1); unpack2(a3, u0, u1);
            Gr[c] = ((x0 + x1) + (y0 + y1)) + ((z0 + z1) + (u0 + u1));
        }
    }
    __syncthreads();

    float lam = 1.f;
    for (int it = 0; it < 56; it++) {
        float s = 0.f;
        if (tid < R) {
            if (R == 8) {
                float2 v0 = *(const float2*)&v[0], v1 = *(const float2*)&v[2];
                float2 v2 = *(const float2*)&v[4], v3 = *(const float2*)&v[6];
                s = ((Gr[0] * v0.x + Gr[1] * v0.y) + (Gr[2] * v1.x + Gr[3] * v1.y))
                  + ((Gr[4] * v2.x + Gr[5] * v2.y) + (Gr[6] * v3.x + Gr[7] * v3.y));
            } else {
                float a0 = 0.f, a1 = 0.f, a2 = 0.f, a3 = 0.f;
                #pragma unroll
                for (int k4 = 0; k4 < 16; k4++) {
                    float4 vv = *(const float4*)&v[k4 * 4];
                    a0 += Gr[k4 * 4]     * vv.x;
                    a1 += Gr[k4 * 4 + 1] * vv.y;
                    a2 += Gr[k4 * 4 + 2] * vv.z;
                    a3 += Gr[k4 * 4 + 3] * vv.w;
                }
                s = (a0 + a1) + (a2 + a3);
            }
        }
        float sq = (tid < R) ? s * s : 0.f;
        #pragma unroll
        for (int off = 16; off > 0; off >>= 1)
            sq += __shfl_xor_sync(0xffffffff, sq, off);
        if ((tid & 31) == 0) red[tid >> 5] = sq;
        __syncthreads();
        float nrm = sqrtf(red[0] + red[1]);
        lam = nrm;                         // ||G v|| -> sigma^2
        if (tid < R) v[tid] = s / nrm;
        __syncthreads();
    }
    if (tid == 0) g_sigma[bid] = sqrtf(lam);
}

// ---------------------------------------------------------------------------
// Kernel 2: projections with FFMA2-packed transposed weights.
// grid 144 x 128 threads (one block/SM). f,g fp32 [c][n]; h -> fp16 [n][c].
// Also computes global max ||f||^2 (one atomic per block).
// ---------------------------------------------------------------------------
__global__ __launch_bounds__(128)
void proj_kernel(const float* __restrict__ x,
                 const float* __restrict__ Wq, const float* __restrict__ bq,
                 const float* __restrict__ Wk, const float* __restrict__ bk,
                 const float* __restrict__ Wv, const float* __restrict__ bv) {
    __shared__ uint64_t sWqP[CC * 4];    // [k][4]  pairs of scaled Wq rows
    __shared__ uint64_t sWkP[CC * 4];    // [k][4]
    __shared__ uint64_t sWvP[CC * 32];   // [k][32] pairs of scaled Wv rows
    __shared__ uint64_t sbqP[4], sbkP[4], sbvP[32];
    __shared__ float    swmax[4];

    const int tid = threadIdx.x;
    const float isq = 1.f / g_sigma[0];
    const float isk = 1.f / g_sigma[1];
    const float isv = 1.f / g_sigma[2];

    // packed transposed weights: sWP[k*P + p] = {W[2p][k], W[2p+1][k]} * is
    for (int e = tid; e < CC * 4; e += 128) {
        int k = e >> 2, p = e & 3;
        sWqP[e] = pack2(Wq[(2 * p) * CC + k] * isq, Wq[(2 * p + 1) * CC + k] * isq);
        sWkP[e] = pack2(Wk[(2 * p) * CC + k] * isk, Wk[(2 * p + 1) * CC + k] * isk);
    }
    for (int e = tid; e < CC * 32; e += 128) {
        int k = e >> 5, p = e & 31;
        sWvP[e] = pack2(Wv[(2 * p) * CC + k] * isv, Wv[(2 * p + 1) * CC + k] * isv);
    }
    if (tid < 4)  { sbqP[tid] = pack2(bq[2 * tid], bq[2 * tid + 1]);
                    sbkP[tid] = pack2(bk[2 * tid], bk[2 * tid + 1]); }
    if (tid < 32) { sbvP[tid] = pack2(bv[2 * tid], bv[2 * tid + 1]); }
    __syncthreads();

    const int t = blockIdx.x * 128 + tid;
    const int b = t / NN;
    const int n = t % NN;

    float xr[CC];
    #pragma unroll
    for (int c = 0; c < CC; c++) xr[c] = x[(b * CC + c) * NN + n];

    // ---- f, g: 4 packed accumulators each ----
    uint64_t fa[4], ga[4];
    #pragma unroll
    for (int p = 0; p < 4; p++) { fa[p] = sbqP[p]; ga[p] = sbkP[p]; }
    #pragma unroll
    for (int k = 0; k < CC; k++) {
        uint64_t xb = pack2(xr[k], xr[k]);
        const uint64_t* wq = &sWqP[k * 4];
        const uint64_t* wk = &sWkP[k * 4];
        #pragma unroll
        for (int p = 0; p < 4; p++) {
            fa[p] = ffma2(xb, wq[p], fa[p]);
            ga[p] = ffma2(xb, wk[p], ga[p]);
        }
    }
    float nf = 0.f;
    #pragma unroll
    for (int p = 0; p < 4; p++) {
        float f0, f1, g0, g1;
        unpack2(fa[p], f0, f1); unpack2(ga[p], g0, g1);
        g_f[(b * C8 + 2 * p) * NN + n]     = f0;
        g_f[(b * C8 + 2 * p + 1) * NN + n] = f1;
        g_g[(b * C8 + 2 * p) * NN + n]     = g0;
        g_g[(b * C8 + 2 * p + 1) * NN + n] = g1;
        nf += f0 * f0 + f1 * f1;
    }

    // block-reduce max ||f||^2, single atomic per block
    float wm = nf;
    #pragma unroll
    for (int off = 16; off > 0; off >>= 1)
        wm = fmaxf(wm, __shfl_xor_sync(0xffffffff, wm, off));
    if ((tid & 31) == 0) swmax[tid >> 5] = wm;
    __syncthreads();
    if (tid == 0) {
        float bm = fmaxf(fmaxf(swmax[0], swmax[1]), fmaxf(swmax[2], swmax[3]));
        atomicMax(&g_kmax2, __float_as_uint(bm));
    }

    // ---- h: 32 packed accumulators, FFMA2 ----
    uint64_t ha[32];
    #pragma unroll
    for (int p = 0; p < 32; p++) ha[p] = sbvP[p];
    #pragma unroll
    for (int k = 0; k < CC; k++) {
        uint64_t xb = pack2(xr[k], xr[k]);
        const uint64_t* wv = &sWvP[k * 32];
        #pragma unroll
        for (int p = 0; p < 32; p++) ha[p] = ffma2(xb, wv[p], ha[p]);
    }
    uint32_t* ht = (uint32_t*)&g_ht[(b * NN + n) * CC];
    #pragma unroll
    for (int p = 0; p < 32; p++) {
        float h0, h1;
        unpack2(ha[p], h0, h1);
        ht[p] = cvt16x2(h1, h0);
    }
}

// ---------------------------------------------------------------------------
// Kernel 3: HMMA flash attention, fixed-M softmax, cp.async double-buffered.
// 4 warps; warp owns a 16-j tile. grid = (144, B, SPLITS).
// ---------------------------------------------------------------------------
__global__ __launch_bounds__(128, 4)
void attn_kernel() {
    __shared__ float  sKt[2][C8][TK];      // keys fp32 [stage][c][i]
    __shared__ __half sVh[2][TK][VPAD];    // values fp16 [stage][i][c]

    const int b    = blockIdx.y;
    const int sp   = blockIdx.z;
    const int tid  = threadIdx.x;
    const int warp = tid >> 5;
    const int lane = tid & 31;
    const int gid  = lane >> 2, tig = lane & 3;
    const int jt   = blockIdx.x * 64 + warp * 16;
    const int j0   = jt + gid, j1 = j0 + 8;

    // queries + fixed per-row log2-domain bound M (Cauchy-Schwarz)
    float q0[C8], q1[C8];
    float nq0 = 0.f, nq1 = 0.f;
    #pragma unroll
    for (int c = 0; c < C8; c++) {
        q0[c] = g_g[(b * C8 + c) * NN + j0]; nq0 += q0[c] * q0[c];
        q1[c] = g_g[(b * C8 + c) * NN + j1]; nq1 += q1[c] * q1[c];
    }
    const float kmax = sqrtf(__uint_as_float(g_kmax2));
    const float M0 = sqrtf(nq0) * kmax * LOG2E - 10.f;
    const float M1 = sqrtf(nq1) * kmax * LOG2E - 10.f;
    const uint64_t M0n = pack2(-M0, -M0);
    const uint64_t M1n = pack2(-M1, -M1);
    uint64_t q2A[C8], q2B[C8];
    #pragma unroll
    for (int c = 0; c < C8; c++) {
        float a = q0[c] * LOG2E, d = q1[c] * LOG2E;
        q2A[c] = pack2(a, a);
        q2B[c] = pack2(d, d);
    }

    float acc[32];
    #pragma unroll
    for (int c = 0; c < 32; c++) acc[c] = 0.f;
    float l0 = 0.f, l1 = 0.f;

    const uint32_t skt_base = (uint32_t)__cvta_generic_to_shared(&sKt[0][0][0]);
    const uint32_t svh_base = (uint32_t)__cvta_generic_to_shared(&sVh[0][0][0]);
    const int lrow = (lane & 7) + ((lane >> 3) & 1) * 8;
    const int lcol = (lane >> 4) * 8;

    const int i_beg = sp * KPS;

    auto prefetch = [&](int tt, int s) {
        const int i0 = i_beg + tt * TK;
        #pragma unroll
        for (int r = 0; r < 2; r++) {
            int e = r * 128 + tid;
            int c = e >> 5, w = e & 31;
            cpa16(skt_base + (uint32_t)(((s * C8 + c) * TK + w * 4) * 4),
                  &g_f[(b * C8 + c) * NN + i0 + w * 4]);
        }
        const __half* vsrc = &g_ht[(b * NN + i0 + tid) * CC];
        const uint32_t vdst = svh_base + (uint32_t)(((s * TK + tid) * VPAD) * 2);
        #pragma unroll
        for (int r = 0; r < 8; r++)
            cpa16(vdst + (uint32_t)(r * 16), vsrc + r * 8);
    };

    prefetch(0, 0);
    cpa_commit();

    for (int tt = 0; tt < NT; tt++) {
        const int s = tt & 1;
        cpa_wait<0>();
        __syncthreads();    // publishes stage s; also fences stage s^1 consumers
        if (tt + 1 < NT) {
            prefetch(tt + 1, s ^ 1);
            cpa_commit();
        }

        const uint32_t svh_s = svh_base + (uint32_t)(s * TK * VPAD * 2);
        for (int t = 0; t < TK; t += 16) {
            const int iA = t + 2 * tig, iB = iA + 8;
            // ---- scores (accumulator pre-seeded with -M) ----
            uint64_t kA = *(const uint64_t*)&sKt[s][0][iA];
            uint64_t kB = *(const uint64_t*)&sKt[s][0][iB];
            uint64_t sA0 = ffma2(q2A[0], kA, M0n), sA1 = ffma2(q2B[0], kA, M1n);
            uint64_t sB0 = ffma2(q2A[0], kB, M0n), sB1 = ffma2(q2B[0], kB, M1n);
            #pragma unroll
            for (int c = 1; c < C8; c++) {
                kA = *(const uint64_t*)&sKt[s][c][iA];
                kB = *(const uint64_t*)&sKt[s][c][iB];
                sA0 = ffma2(q2A[c], kA, sA0);
                sA1 = ffma2(q2B[c], kA, sA1);
                sB0 = ffma2(q2A[c], kB, sB0);
                sB1 = ffma2(q2B[c], kB, sB1);
            }
            float sA0l, sA0h, sA1l, sA1h, sB0l, sB0h, sB1l, sB1h;
            unpack2(sA0, sA0l, sA0h); unpack2(sA1, sA1l, sA1h);
            unpack2(sB0, sB0l, sB0h); unpack2(sB1, sB1l, sB1h);
            // ---- p = 2^(s-M), independent MUFUs ----
            float p00 = ex2(sA0l), p01 = ex2(sA0h);
            float p02 = ex2(sB0l), p03 = ex2(sB0h);
            float p10 = ex2(sA1l), p11 = ex2(sA1h);
            float p12 = ex2(sB1l), p13 = ex2(sB1h);
            l0 += (p00 + p01) + (p02 + p03);
            l1 += (p10 + p11) + (p12 + p13);
            uint32_t a0 = cvt16x2(p01, p00);
            uint32_t a1 = cvt16x2(p11, p10);
            uint32_t a2 = cvt16x2(p03, p02);
            uint32_t a3 = cvt16x2(p13, p12);
            // ---- V fragments + MMAs ----
            uint32_t rowaddr = svh_s + (uint32_t)((t + lrow) * (VPAD * 2) + lcol * 2);
            #pragma unroll
            for (int g = 0; g < 4; g++) {
                uint32_t b0, b1, b2, b3;
                ldmx4t(b0, b1, b2, b3, rowaddr + (uint32_t)(g * 32));
                float* d = &acc[g * 8];
                mma16816(d[0], d[1], d[2], d[3], a0, a1, a2, a3, b0, b1);
                mma16816(d[4], d[5], d[6], d[7], a0, a1, a2, a3, b2, b3);
            }
        }
        // no tail barrier: top-of-loop __syncthreads() orders stage reuse
    }

    l0 += __shfl_xor_sync(0xffffffff, l0, 1);
    l0 += __shfl_xor_sync(0xffffffff, l0, 2);
    l1 += __shfl_xor_sync(0xffffffff, l1, 1);
    l1 += __shfl_xor_sync(0xffffffff, l1, 2);

    const int ps = b * SPLITS + sp;
    if (tig == 0) {
        g_pl[ps * NN + j0] = l0;
        g_pl[ps * NN + j1] = l1;
    }
    #pragma unroll
    for (int nt = 0; nt < 8; nt++) {
        const int c = nt * 8 + 2 * tig;
        g_pacc[(ps * CC + c)     * NN + j0] = acc[nt * 4 + 0];
        g_pacc[(ps * CC + c + 1) * NN + j0] = acc[nt * 4 + 1];
        g_pacc[(ps * CC + c)     * NN + j1] = acc[nt * 4 + 2];
        g_pacc[(ps * CC + c + 1) * NN + j1] = acc[nt * 4 + 3];
    }
}

// ---------------------------------------------------------------------------
// Kernel 4: combine split partials (plain sums), residual. grid (72, 16),
// 4 channels per block -> 1152 blocks, DRAM-roofline parallelism.
// ---------------------------------------------------------------------------
__global__ __launch_bounds__(256)
void reduce_kernel(const float* __restrict__ x,
                   const float* __restrict__ gamma,
                   float* __restrict__ out) {
    const int t  = blockIdx.x * 256 + threadIdx.x;
    const int b  = t / NN;
    const int j  = t % NN;
    const int c0 = blockIdx.y * 4;

    float L = 0.f;
    #pragma unroll
    for (int s = 0; s < SPLITS; s++) L += g_pl[(b * SPLITS + s) * NN + j];
    const float inv = gamma[0] / L;

    #pragma unroll
    for (int c = c0; c < c0 + 4; c++) {
        float a = 0.f;
        #pragma unroll
        for (int s = 0; s < SPLITS; s++)
            a += g_pacc[((b * SPLITS + s) * CC + c) * NN + j];
        const int idx = (b * CC + c) * NN + j;
        out[idx] = a * inv + x[idx];
    }
}

// ---------------------------------------------------------------------------
extern "C" void kernel_launch(void* const* d_in, const int* in_sizes, int n_in,
                              void* d_out, int out_size) {
    const float* x     = (const float*)d_in[0];
    const float* Wq    = (const float*)d_in[1];
    const float* bq    = (const float*)d_in[2];
    const float* Wk    = (const float*)d_in[3];
    const float* bk    = (const float*)d_in[4];
    const float* Wv    = (const float*)d_in[5];
    const float* bv    = (const float*)d_in[6];
    const float* gamma = (const float*)d_in[7];
    float* out = (float*)d_out;

    sigma_kernel<<<3, 64>>>(Wq, Wk, Wv);
    proj_kernel<<<(BB * NN) / 128, 128>>>(x, Wq, bq, Wk, bk, Wv, bv);
    attn_kernel<<<dim3(NN / 64, BB, SPLITS), 128>>>();
    reduce_kernel<<<dim3((BB * NN) / 256, 16), 256>>>(x, gamma, out);
}

// round 13
// speedup vs baseline: 9.8021x; 1.1177x over previous
#include <cuda_runtime.h>
#include <cuda_fp16.h>
#include <math.h>
#include <stdint.h>

#define CC     64
#define C8     8
#define NN     9216
#define BB     2
#define SPLITS 2
#define KPS    (NN / SPLITS)    // 4608 keys per split
#define TK     128              // keys staged per smem tile
#define NT     (KPS / TK)       // 36 tiles per block
#define VPAD   72               // sVh row pitch in halves (144B)
#define KROW   136              // sKh/sKl row pitch in halves (272B: rotates banks)
#define LOG2E  1.44269504088896340736f

// Scratch (no allocations allowed in kernel_launch)
__device__ float        g_sigma[3];
__device__ unsigned int g_kmax2;                   // max ||f_i||^2 (bits of nonneg float)
__device__ __half       g_fh[BB * C8 * NN];        // keys fp16 hi  [B, 8, N]
__device__ __half       g_fl[BB * C8 * NN];        // keys fp16 lo  [B, 8, N]
__device__ float        g_g[BB * C8 * NN];         // queries [B, 8, N] fp32
__device__ __half       g_ht[BB * NN * CC];        // values  [B, N, 64] fp16 (row-major)
__device__ float        g_pl[BB * SPLITS * NN];    // split partial denominators
__device__ float        g_pacc[BB * SPLITS * CC * NN];  // split partial numerators

// ---- packed f32x2 helpers (SASS FFMA2) ----
__device__ __forceinline__ uint64_t pack2(float lo, float hi) {
    uint64_t r; asm("mov.b64 %0, {%1, %2};" : "=l"(r) : "f"(lo), "f"(hi)); return r;
}
__device__ __forceinline__ uint64_t ffma2(uint64_t a, uint64_t b, uint64_t c) {
    uint64_t d; asm("fma.rn.f32x2 %0, %1, %2, %3;" : "=l"(d) : "l"(a), "l"(b), "l"(c)); return d;
}
__device__ __forceinline__ void unpack2(uint64_t v, float& lo, float& hi) {
    asm("mov.b64 {%0, %1}, %2;" : "=f"(lo), "=f"(hi) : "l"(v));
}
__device__ __forceinline__ float ex2(float x) {
    float r; asm("ex2.approx.f32 %0, %1;" : "=f"(r) : "f"(x)); return r;
}
// d = {lo, hi} packed fp16x2 (first asm source -> high half)
__device__ __forceinline__ uint32_t cvt16x2(float hi, float lo) {
    uint32_t d; asm("cvt.rn.f16x2.f32 %0, %1, %2;" : "=r"(d) : "f"(hi), "f"(lo)); return d;
}
__device__ __forceinline__ void mma16816(float& d0, float& d1, float& d2, float& d3,
                                         uint32_t a0, uint32_t a1, uint32_t a2, uint32_t a3,
                                         uint32_t b0, uint32_t b1) {
    asm volatile("mma.sync.aligned.m16n8k16.row.col.f32.f16.f16.f32 "
                 "{%0,%1,%2,%3}, {%4,%5,%6,%7}, {%8,%9}, {%0,%1,%2,%3};"
                 : "+f"(d0), "+f"(d1), "+f"(d2), "+f"(d3)
                 : "r"(a0), "r"(a1), "r"(a2), "r"(a3), "r"(b0), "r"(b1));
}
__device__ __forceinline__ void mma16808(float& d0, float& d1, float& d2, float& d3,
                                         uint32_t a0, uint32_t a1, uint32_t b0) {
    asm volatile("mma.sync.aligned.m16n8k8.row.col.f32.f16.f16.f32 "
                 "{%0,%1,%2,%3}, {%4,%5}, {%6}, {%0,%1,%2,%3};"
                 : "+f"(d0), "+f"(d1), "+f"(d2), "+f"(d3)
                 : "r"(a0), "r"(a1), "r"(b0));
}
__device__ __forceinline__ void ldmx4t(uint32_t& b0, uint32_t& b1, uint32_t& b2, uint32_t& b3,
                                       uint32_t smaddr) {
    asm volatile("ldmatrix.sync.aligned.m8n8.x4.trans.shared.b16 {%0,%1,%2,%3}, [%4];"
                 : "=r"(b0), "=r"(b1), "=r"(b2), "=r"(b3) : "r"(smaddr));
}
__device__ __forceinline__ void ldmx2t(uint32_t& b0, uint32_t& b1, uint32_t smaddr) {
    asm volatile("ldmatrix.sync.aligned.m8n8.x2.trans.shared.b16 {%0,%1}, [%2];"
                 : "=r"(b0), "=r"(b1) : "r"(smaddr));
}
// ---- cp.async (LDGSTS) ----
__device__ __forceinline__ void cpa16(uint32_t dst, const void* src) {
    asm volatile("cp.async.cg.shared.global [%0], [%1], 16;" :: "r"(dst), "l"(src));
}
__device__ __forceinline__ void cpa_commit() {
    asm volatile("cp.async.commit_group;");
}
template <int N>
__device__ __forceinline__ void cpa_wait() {
    asm volatile("cp.async.wait_group %0;" :: "n"(N));
}

// ---------------------------------------------------------------------------
// Kernel 1: spectral norms via power iteration on Gram matrix G = W W^T.
// ---------------------------------------------------------------------------
__global__ __launch_bounds__(64)
void sigma_kernel(const float* __restrict__ Wq,
                  const float* __restrict__ Wk,
                  const float* __restrict__ Wv) {
    __shared__ float sW[64 * 64];
    __shared__ float v[64];
    __shared__ float red[2];
    const int bid = blockIdx.x;
    const int tid = threadIdx.x;
    if (bid == 0 && tid == 0) g_kmax2 = 0u;
    const float* W = (bid == 0) ? Wq : ((bid == 1) ? Wk : Wv);
    const int R = (bid == 2) ? 64 : 8;

    for (int e = tid; e < R * 64; e += 64) sW[e] = W[e];
    if (tid < R) v[tid] = 1.f;
    __syncthreads();

    float Gr[64];
    if (tid < R) {
        uint64_t w2[32];
        const uint64_t* wrp = (const uint64_t*)&sW[tid * 64];
        #pragma unroll
        for (int i = 0; i < 32; i++) w2[i] = wrp[i];
        for (int c = 0; c < R; c++) {
            const uint64_t* wcp = (const uint64_t*)&sW[c * 64];   // broadcast
            uint64_t a0 = 0ull, a1 = 0ull, a2 = 0ull, a3 = 0ull;
            #pragma unroll
            for (int kk = 0; kk < 32; kk += 4) {
                a0 = ffma2(w2[kk],     wcp[kk],     a0);
                a1 = ffma2(w2[kk + 1], wcp[kk + 1], a1);
                a2 = ffma2(w2[kk + 2], wcp[kk + 2], a2);
                a3 = ffma2(w2[kk + 3], wcp[kk + 3], a3);
            }
            float x0, x1, y0, y1, z0, z1, u0, u1;
            unpack2(a0, x0, x1); unpack2(a1, y0, y1);
            unpack2(a2, z0, z1); unpack2(a3, u0, u1);
            Gr[c] = ((x0 + x1) + (y0 + y1)) + ((z0 + z1) + (u0 + u1));
        }
    }
    __syncthreads();

    float lam = 1.f;
    for (int it = 0; it < 56; it++) {
        float s = 0.f;
        if (tid < R) {
            if (R == 8) {
                float2 v0 = *(const float2*)&v[0], v1 = *(const float2*)&v[2];
                float2 v2 = *(const float2*)&v[4], v3 = *(const float2*)&v[6];
                s = ((Gr[0] * v0.x + Gr[1] * v0.y) + (Gr[2] * v1.x + Gr[3] * v1.y))
                  + ((Gr[4] * v2.x + Gr[5] * v2.y) + (Gr[6] * v3.x + Gr[7] * v3.y));
            } else {
                float a0 = 0.f, a1 = 0.f, a2 = 0.f, a3 = 0.f;
                #pragma unroll
                for (int k4 = 0; k4 < 16; k4++) {
                    float4 vv = *(const float4*)&v[k4 * 4];
                    a0 += Gr[k4 * 4]     * vv.x;
                    a1 += Gr[k4 * 4 + 1] * vv.y;
                    a2 += Gr[k4 * 4 + 2] * vv.z;
                    a3 += Gr[k4 * 4 + 3] * vv.w;
                }
                s = (a0 + a1) + (a2 + a3);
            }
        }
        float sq = (tid < R) ? s * s : 0.f;
        #pragma unroll
        for (int off = 16; off > 0; off >>= 1)
            sq += __shfl_xor_sync(0xffffffff, sq, off);
        if ((tid & 31) == 0) red[tid >> 5] = sq;
        __syncthreads();
        float nrm = sqrtf(red[0] + red[1]);
        lam = nrm;                         // ||G v|| -> sigma^2
        if (tid < R) v[tid] = s / nrm;
        __syncthreads();
    }
    if (tid == 0) g_sigma[bid] = sqrtf(lam);
}

// ---------------------------------------------------------------------------
// Kernel 2: projections with FFMA2-packed transposed weights.
// keys -> fp16 hi/lo planes [c][n]; queries fp32 [c][n]; h -> fp16 [n][c].
// Also computes global max ||f||^2 (one atomic per block).
// ---------------------------------------------------------------------------
__global__ __launch_bounds__(128)
void proj_kernel(const float* __restrict__ x,
                 const float* __restrict__ Wq, const float* __restrict__ bq,
                 const float* __restrict__ Wk, const float* __restrict__ bk,
                 const float* __restrict__ Wv, const float* __restrict__ bv) {
    __shared__ uint64_t sWqP[CC * 4];    // [k][4]  pairs of scaled Wq rows
    __shared__ uint64_t sWkP[CC * 4];    // [k][4]
    __shared__ uint64_t sWvP[CC * 32];   // [k][32] pairs of scaled Wv rows
    __shared__ uint64_t sbqP[4], sbkP[4], sbvP[32];
    __shared__ float    swmax[4];

    const int tid = threadIdx.x;
    const float isq = 1.f / g_sigma[0];
    const float isk = 1.f / g_sigma[1];
    const float isv = 1.f / g_sigma[2];

    for (int e = tid; e < CC * 4; e += 128) {
        int k = e >> 2, p = e & 3;
        sWqP[e] = pack2(Wq[(2 * p) * CC + k] * isq, Wq[(2 * p + 1) * CC + k] * isq);
        sWkP[e] = pack2(Wk[(2 * p) * CC + k] * isk, Wk[(2 * p + 1) * CC + k] * isk);
    }
    for (int e = tid; e < CC * 32; e += 128) {
        int k = e >> 5, p = e & 31;
        sWvP[e] = pack2(Wv[(2 * p) * CC + k] * isv, Wv[(2 * p + 1) * CC + k] * isv);
    }
    if (tid < 4)  { sbqP[tid] = pack2(bq[2 * tid], bq[2 * tid + 1]);
                    sbkP[tid] = pack2(bk[2 * tid], bk[2 * tid + 1]); }
    if (tid < 32) { sbvP[tid] = pack2(bv[2 * tid], bv[2 * tid + 1]); }
    __syncthreads();

    const int t = blockIdx.x * 128 + tid;
    const int b = t / NN;
    const int n = t % NN;

    float xr[CC];
    #pragma unroll
    for (int c = 0; c < CC; c++) xr[c] = x[(b * CC + c) * NN + n];

    // ---- f (keys), g (queries): 4 packed accumulators each ----
    uint64_t fa[4], ga[4];
    #pragma unroll
    for (int p = 0; p < 4; p++) { fa[p] = sbqP[p]; ga[p] = sbkP[p]; }
    #pragma unroll
    for (int k = 0; k < CC; k++) {
        uint64_t xb = pack2(xr[k], xr[k]);
        const uint64_t* wq = &sWqP[k * 4];
        const uint64_t* wk = &sWkP[k * 4];
        #pragma unroll
        for (int p = 0; p < 4; p++) {
            fa[p] = ffma2(xb, wq[p], fa[p]);
            ga[p] = ffma2(xb, wk[p], ga[p]);
        }
    }
    float nf = 0.f;
    #pragma unroll
    for (int p = 0; p < 4; p++) {
        float f0, f1, g0, g1;
        unpack2(fa[p], f0, f1); unpack2(ga[p], g0, g1);
        // keys: fp16 hi/lo split (exact to ~2^-22)
        const int i0 = (b * C8 + 2 * p) * NN + n;
        const int i1 = (b * C8 + 2 * p + 1) * NN + n;
        __half h0 = __float2half_rn(f0), h1 = __float2half_rn(f1);
        g_fh[i0] = h0;  g_fl[i0] = __float2half_rn(f0 - __half2float(h0));
        g_fh[i1] = h1;  g_fl[i1] = __float2half_rn(f1 - __half2float(h1));
        g_g[i0] = g0;
        g_g[i1] = g1;
        nf += f0 * f0 + f1 * f1;
    }

    float wm = nf;
    #pragma unroll
    for (int off = 16; off > 0; off >>= 1)
        wm = fmaxf(wm, __shfl_xor_sync(0xffffffff, wm, off));
    if ((tid & 31) == 0) swmax[tid >> 5] = wm;
    __syncthreads();
    if (tid == 0) {
        float bm = fmaxf(fmaxf(swmax[0], swmax[1]), fmaxf(swmax[2], swmax[3]));
        atomicMax(&g_kmax2, __float_as_uint(bm));
    }

    // ---- h: 32 packed accumulators, FFMA2 ----
    uint64_t ha[32];
    #pragma unroll
    for (int p = 0; p < 32; p++) ha[p] = sbvP[p];
    #pragma unroll
    for (int k = 0; k < CC; k++) {
        uint64_t xb = pack2(xr[k], xr[k]);
        const uint64_t* wv = &sWvP[k * 32];
        #pragma unroll
        for (int p = 0; p < 32; p++) ha[p] = ffma2(xb, wv[p], ha[p]);
    }
    uint32_t* ht = (uint32_t*)&g_ht[(b * NN + n) * CC];
    #pragma unroll
    for (int p = 0; p < 32; p++) {
        float h0, h1;
        unpack2(ha[p], h0, h1);
        ht[p] = cvt16x2(h1, h0);
    }
}

// ---------------------------------------------------------------------------
// Kernel 3: full-HMMA flash attention, fixed-M softmax, cp.async pipeline.
// QK: hi/lo-split fp16 MMA (m16n8k8, 3 terms) with -M seeded in C -> exact
// log2-domain scores in the C fragment; 8 MUFU exps; PV: m16n8k16 vs
// ldmatrix'd fp16 V. 4 warps, warp owns 16 j. grid = (144, B, SPLITS).
// ---------------------------------------------------------------------------
__global__ __launch_bounds__(128, 4)
void attn_kernel() {
    __shared__ __align__(16) __half sKh[2][C8][KROW];   // key hi [stage][c][i]
    __shared__ __align__(16) __half sKl[2][C8][KROW];   // key lo
    __shared__ __align__(16) __half sVh[2][TK][VPAD];   // values [stage][i][c]

    const int b    = blockIdx.y;
    const int sp   = blockIdx.z;
    const int tid  = threadIdx.x;
    const int warp = tid >> 5;
    const int lane = tid & 31;
    const int gid  = lane >> 2, tig = lane & 3;
    const int jt   = blockIdx.x * 64 + warp * 16;
    const int j0   = jt + gid, j1 = j0 + 8;

    // queries + fixed per-row log2-domain bound M (Cauchy-Schwarz)
    float q0[C8], q1[C8];
    float nq0 = 0.f, nq1 = 0.f;
    #pragma unroll
    for (int c = 0; c < C8; c++) {
        q0[c] = g_g[(b * C8 + c) * NN + j0]; nq0 += q0[c] * q0[c];
        q1[c] = g_g[(b * C8 + c) * NN + j1]; nq1 += q1[c] * q1[c];
    }
    const float kmax = sqrtf(__uint_as_float(g_kmax2));
    const float M0 = sqrtf(nq0) * kmax * LOG2E - 10.f;
    const float M1 = sqrtf(nq1) * kmax * LOG2E - 10.f;

    // Q A-fragments for m16n8k8 (k = channels 2*tig, 2*tig+1), hi/lo split
    const int c0 = 2 * tig, c1 = c0 + 1;
    const float qs00 = q0[c0] * LOG2E, qs01 = q0[c1] * LOG2E;
    const float qs10 = q1[c0] * LOG2E, qs11 = q1[c1] * LOG2E;
    const uint32_t aqh0 = cvt16x2(qs01, qs00);         // row j0
    const uint32_t aqh1 = cvt16x2(qs11, qs10);         // row j1
    __half2 hq0 = *(const __half2*)&aqh0;
    __half2 hq1 = *(const __half2*)&aqh1;
    const uint32_t aql0 = cvt16x2(qs01 - __high2float(hq0), qs00 - __low2float(hq0));
    const uint32_t aql1 = cvt16x2(qs11 - __high2float(hq1), qs10 - __low2float(hq1));

    float acc[32];
    #pragma unroll
    for (int c = 0; c < 32; c++) acc[c] = 0.f;
    float l0 = 0.f, l1 = 0.f;

    const uint32_t skh_base = (uint32_t)__cvta_generic_to_shared(&sKh[0][0][0]);
    const uint32_t skl_base = (uint32_t)__cvta_generic_to_shared(&sKl[0][0][0]);
    const uint32_t svh_base = (uint32_t)__cvta_generic_to_shared(&sVh[0][0][0]);
    const int lrow = (lane & 7) + ((lane >> 3) & 1) * 8;   // V ldmatrix row
    const int lcol = (lane >> 4) * 8;                      // V ldmatrix col
    const int kal  = lane & 7;                             // K ldmatrix: channel row
    const int kgrp = (lane >> 3) & 1;                      // K ldmatrix: n-group (iA/iB)

    const int i_beg = sp * KPS;

    auto prefetch = [&](int tt, int s) {
        const int i0 = i_beg + tt * TK;
        {   // K hi/lo: 8 rows x 16 chunks of 16B each (128 threads exactly)
            int c = tid >> 4, w = tid & 15;
            cpa16(skh_base + (uint32_t)(((s * C8 + c) * KROW + w * 8) * 2),
                  &g_fh[(b * C8 + c) * NN + i0 + w * 8]);
            cpa16(skl_base + (uint32_t)(((s * C8 + c) * KROW + w * 8) * 2),
                  &g_fl[(b * C8 + c) * NN + i0 + w * 8]);
        }
        const __half* vsrc = &g_ht[(b * NN + i0 + tid) * CC];
        const uint32_t vdst = svh_base + (uint32_t)(((s * TK + tid) * VPAD) * 2);
        #pragma unroll
        for (int r = 0; r < 8; r++)
            cpa16(vdst + (uint32_t)(r * 16), vsrc + r * 8);
    };

    prefetch(0, 0);
    cpa_commit();

    for (int tt = 0; tt < NT; tt++) {
        const int s = tt & 1;
        cpa_wait<0>();
        __syncthreads();    // publishes stage s; orders reuse of the other stage
        if (tt + 1 < NT) {
            prefetch(tt + 1, s ^ 1);
            cpa_commit();
        }

        const uint32_t skh_s = skh_base + (uint32_t)(s * C8 * KROW * 2);
        const uint32_t skl_s = skl_base + (uint32_t)(s * C8 * KROW * 2);
        const uint32_t svh_s = svh_base + (uint32_t)(s * TK * VPAD * 2);

        for (int t = 0; t < TK; t += 16) {
            // ---- K B-fragments (hi & lo), 2 n-groups each ----
            const uint32_t koff = (uint32_t)((kal * KROW + t + kgrp * 8) * 2);
            uint32_t kh0, kh1, kl0, kl1;
            ldmx2t(kh0, kh1, skh_s + koff);
            ldmx2t(kl0, kl1, skl_s + koff);
            // ---- scores: 3-term hi/lo MMA, -M pre-seeded ----
            float dA0 = -M0, dA1 = -M0, dA2 = -M1, dA3 = -M1;
            float dB0 = -M0, dB1 = -M0, dB2 = -M1, dB3 = -M1;
            mma16808(dA0, dA1, dA2, dA3, aqh0, aqh1, kh0);
            mma16808(dB0, dB1, dB2, dB3, aqh0, aqh1, kh1);
            mma16808(dA0, dA1, dA2, dA3, aqh0, aqh1, kl0);
            mma16808(dB0, dB1, dB2, dB3, aqh0, aqh1, kl1);
            mma16808(dA0, dA1, dA2, dA3, aql0, aql1, kh0);
            mma16808(dB0, dB1, dB2, dB3, aql0, aql1, kh1);
            // ---- p = 2^(s-M) ----
            float p00 = ex2(dA0), p01 = ex2(dA1), p10 = ex2(dA2), p11 = ex2(dA3);
            float p02 = ex2(dB0), p03 = ex2(dB1), p12 = ex2(dB2), p13 = ex2(dB3);
            l0 += (p00 + p01) + (p02 + p03);
            l1 += (p10 + p11) + (p12 + p13);
            uint32_t a0 = cvt16x2(p01, p00);
            uint32_t a1 = cvt16x2(p11, p10);
            uint32_t a2 = cvt16x2(p03, p02);
            uint32_t a3 = cvt16x2(p13, p12);
            // ---- V fragments + PV MMAs ----
            uint32_t rowaddr = svh_s + (uint32_t)((t + lrow) * (VPAD * 2) + lcol * 2);
            #pragma unroll
            for (int g = 0; g < 4; g++) {
                uint32_t b0, b1, b2, b3;
                ldmx4t(b0, b1, b2, b3, rowaddr + (uint32_t)(g * 32));
                float* d = &acc[g * 8];
                mma16816(d[0], d[1], d[2], d[3], a0, a1, a2, a3, b0, b1);
                mma16816(d[4], d[5], d[6], d[7], a0, a1, a2, a3, b2, b3);
            }
        }
    }

    l0 += __shfl_xor_sync(0xffffffff, l0, 1);
    l0 += __shfl_xor_sync(0xffffffff, l0, 2);
    l1 += __shfl_xor_sync(0xffffffff, l1, 1);
    l1 += __shfl_xor_sync(0xffffffff, l1, 2);

    const int ps = b * SPLITS + sp;
    if (tig == 0) {
        g_pl[ps * NN + j0] = l0;
        g_pl[ps * NN + j1] = l1;
    }
    #pragma unroll
    for (int nt = 0; nt < 8; nt++) {
        const int c = nt * 8 + 2 * tig;
        g_pacc[(ps * CC + c)     * NN + j0] = acc[nt * 4 + 0];
        g_pacc[(ps * CC + c + 1) * NN + j0] = acc[nt * 4 + 1];
        g_pacc[(ps * CC + c)     * NN + j1] = acc[nt * 4 + 2];
        g_pacc[(ps * CC + c + 1) * NN + j1] = acc[nt * 4 + 3];
    }
}

// ---------------------------------------------------------------------------
// Kernel 4: combine split partials (plain sums), residual. grid (72, 16).
// ---------------------------------------------------------------------------
__global__ __launch_bounds__(256)
void reduce_kernel(const float* __restrict__ x,
                   const float* __restrict__ gamma,
                   float* __restrict__ out) {
    const int t  = blockIdx.x * 256 + threadIdx.x;
    const int b  = t / NN;
    const int j  = t % NN;
    const int c0 = blockIdx.y * 4;

    float L = 0.f;
    #pragma unroll
    for (int s = 0; s < SPLITS; s++) L += g_pl[(b * SPLITS + s) * NN + j];
    const float inv = gamma[0] / L;

    #pragma unroll
    for (int c = c0; c < c0 + 4; c++) {
        float a = 0.f;
        #pragma unroll
        for (int s = 0; s < SPLITS; s++)
            a += g_pacc[((b * SPLITS + s) * CC + c) * NN + j];
        const int idx = (b * CC + c) * NN + j;
        out[idx] = a * inv + x[idx];
    }
}

// ---------------------------------------------------------------------------
extern "C" void kernel_launch(void* const* d_in, const int* in_sizes, int n_in,
                              void* d_out, int out_size) {
    const float* x     = (const float*)d_in[0];
    const float* Wq    = (const float*)d_in[1];
    const float* bq    = (const float*)d_in[2];
    const float* Wk    = (const float*)d_in[3];
    const float* bk    = (const float*)d_in[4];
    const float* Wv    = (const float*)d_in[5];
    const float* bv    = (const float*)d_in[6];
    const float* gamma = (const float*)d_in[7];
    float* out = (float*)d_out;

    sigma_kernel<<<3, 64>>>(Wq, Wk, Wv);
    proj_kernel<<<(BB * NN) / 128, 128>>>(x, Wq, bq, Wk, bk, Wv, bv);
    attn_kernel<<<dim3(NN / 64, BB, SPLITS), 128>>>();
    reduce_kernel<<<dim3((BB * NN) / 256, 16), 256>>>(x, gamma, out);
}